// round 12
// baseline (speedup 1.0000x reference)
#include <cuda_runtime.h>
#include <cuda_bf16.h>
#include <cfloat>
#include <math.h>
#include <cstdint>

#define T_TOK   2048
#define D_DIM   768
#define H_HEADS 4
#define N_KEYS  25600
#define KD      128
#define KNN     16
#define HID_A   44
#define HID_S   1024
#define QDIM    (H_HEADS*KD)   // 512
#define BN_EPS  1e-5f

#define KEY_SPLITS 4
#define KEYS_PER_SPLIT (N_KEYS / KEY_SPLITS)   // 6400
#define CHUNK_N 64
#define NCHUNK (KEYS_PER_SPLIT / CHUNK_N)      // 100
#define TOK_TILE 128
#define NCAND  (KEY_SPLITS * KNN)              // 64 candidates per (token, head)

// ---------------- scratch (device globals; no allocations allowed) ----------
__device__ __nv_bfloat16 g_qhi[T_TOK * QDIM];
__device__ float g_qf[T_TOK * QDIM];
__device__ __nv_bfloat16 g_khi[H_HEADS * N_KEYS * KD];
__device__ int   g_ptopi[T_TOK * H_HEADS * NCAND];
__device__ int   g_topidx[T_TOK * H_HEADS * KNN];
__device__ float g_gates[T_TOK * H_HEADS * KNN];
__device__ float g_comb[T_TOK];
__device__ float g_bnA[QDIM];
__device__ float g_bnB[QDIM];
// bf16 hi/lo operand splits
__device__ __nv_bfloat16 g_xhi[T_TOK * D_DIM];
__device__ __nv_bfloat16 g_xlo[T_TOK * D_DIM];
__device__ __nv_bfloat16 g_wqhi[QDIM * D_DIM];
__device__ __nv_bfloat16 g_wqlo[QDIM * D_DIM];
__device__ __nv_bfloat16 g_w1hi[HID_S * D_DIM];
__device__ __nv_bfloat16 g_w1lo[HID_S * D_DIM];
__device__ __nv_bfloat16 g_w3hi[HID_S * D_DIM];
__device__ __nv_bfloat16 g_w3lo[HID_S * D_DIM];
__device__ __nv_bfloat16 g_w2hi[D_DIM * HID_S];
__device__ __nv_bfloat16 g_w2lo[D_DIM * HID_S];
__device__ __nv_bfloat16 g_hidhi[T_TOK * HID_S];
__device__ __nv_bfloat16 g_hidlo[T_TOK * HID_S];

// ============================================================================
// helpers
// ============================================================================
__device__ __forceinline__ uint32_t smem_u32(const void* p) {
    uint32_t a;
    asm("{ .reg .u64 t; cvta.to.shared.u64 t, %1; cvt.u32.u64 %0, t; }" : "=r"(a) : "l"(p));
    return a;
}
#define CP_ASYNC16(dst, src) \
    asm volatile("cp.async.cg.shared.global [%0], [%1], 16;" :: "r"((uint32_t)(dst)), "l"(src))
#define CP_COMMIT() asm volatile("cp.async.commit_group;" ::: "memory")
#define CP_WAIT0()  asm volatile("cp.async.wait_group 0;" ::: "memory")

__device__ __forceinline__ void ldmx4(uint32_t& r0, uint32_t& r1, uint32_t& r2, uint32_t& r3,
                                      uint32_t addr) {
    asm volatile("ldmatrix.sync.aligned.m8n8.x4.shared.b16 {%0,%1,%2,%3}, [%4];"
                 : "=r"(r0), "=r"(r1), "=r"(r2), "=r"(r3) : "r"(addr));
}
__device__ __forceinline__ void mma_bf16(float* c, const uint32_t* a, const uint32_t* b) {
    asm volatile(
        "mma.sync.aligned.m16n8k16.row.col.f32.bf16.bf16.f32 "
        "{%0,%1,%2,%3}, {%4,%5,%6,%7}, {%8,%9}, {%0,%1,%2,%3};"
        : "+f"(c[0]), "+f"(c[1]), "+f"(c[2]), "+f"(c[3])
        : "r"(a[0]), "r"(a[1]), "r"(a[2]), "r"(a[3]), "r"(b[0]), "r"(b[1]));
}

// fully unrolled register insertion into sorted-desc list of 16
__device__ __forceinline__ void reg_insert16(float* tv, int* ti, float vv, int idx) {
#pragma unroll
    for (int p = KNN - 1; p > 0; --p) {
        bool shift = tv[p - 1] < vv;
        bool here  = !shift && (tv[p] < vv);
        float ntv = shift ? tv[p - 1] : (here ? vv : tv[p]);
        int   nti = shift ? ti[p - 1] : (here ? idx : ti[p]);
        tv[p] = ntv; ti[p] = nti;
    }
    if (tv[0] < vv) { tv[0] = vv; ti[0] = idx; }
}

// ============================================================================
// prep_all: keysprep + split(x) + split(wq) + bnprep in one launch
// ============================================================================
#define PREP_KEY_BLKS ((H_HEADS * N_KEYS * KD) / (256 * 4))
#define PREP_X_BLKS   ((T_TOK * D_DIM) / (256 * 4))
#define PREP_WQ_BLKS  ((QDIM * D_DIM) / (256 * 4))
#define PREP_BN_BLKS  ((QDIM + 255) / 256)
#define PREP_TOTAL_BLKS (PREP_KEY_BLKS + PREP_X_BLKS + PREP_WQ_BLKS + PREP_BN_BLKS)

__global__ void prep_all_kernel(const float* __restrict__ keys,
                                const float* __restrict__ x,
                                const float* __restrict__ wq,
                                const float* __restrict__ bq,
                                const float* __restrict__ gamma,
                                const float* __restrict__ beta,
                                const float* __restrict__ mean,
                                const float* __restrict__ var)
{
    int b = blockIdx.x;
    if (b < PREP_KEY_BLKS) {
        size_t i = (size_t)b * 256 + threadIdx.x;
        const float4 v = ((const float4*)keys)[i];
        ((__nv_bfloat162*)g_khi)[2 * i] =
            __nv_bfloat162(__float2bfloat16(v.x), __float2bfloat16(v.y));
        ((__nv_bfloat162*)g_khi)[2 * i + 1] =
            __nv_bfloat162(__float2bfloat16(v.z), __float2bfloat16(v.w));
        return;
    }
    b -= PREP_KEY_BLKS;
    if (b < PREP_X_BLKS + PREP_WQ_BLKS) {
        const float* src;
        __nv_bfloat16 *hi, *lo;
        size_t i;
        if (b < PREP_X_BLKS) {
            src = x; hi = g_xhi; lo = g_xlo;
            i = (size_t)b * 256 + threadIdx.x;
        } else {
            src = wq; hi = g_wqhi; lo = g_wqlo;
            i = (size_t)(b - PREP_X_BLKS) * 256 + threadIdx.x;
        }
        float4 v = ((const float4*)src)[i];
        float f[4] = {v.x, v.y, v.z, v.w};
        __nv_bfloat16 h[4], l[4];
#pragma unroll
        for (int k = 0; k < 4; ++k) {
            h[k] = __float2bfloat16(f[k]);
            l[k] = __float2bfloat16(f[k] - __bfloat162float(h[k]));
        }
        ((__nv_bfloat162*)hi)[2 * i]     = __nv_bfloat162(h[0], h[1]);
        ((__nv_bfloat162*)hi)[2 * i + 1] = __nv_bfloat162(h[2], h[3]);
        ((__nv_bfloat162*)lo)[2 * i]     = __nv_bfloat162(l[0], l[1]);
        ((__nv_bfloat162*)lo)[2 * i + 1] = __nv_bfloat162(l[2], l[3]);
        return;
    }
    b -= PREP_X_BLKS + PREP_WQ_BLKS;
    {
        int n = b * 256 + threadIdx.x;
        if (n < QDIM) {
            float sc = gamma[n] * rsqrtf(var[n] + BN_EPS);
            g_bnA[n] = sc;
            g_bnB[n] = (bq[n] - mean[n]) * sc + beta[n];
        }
    }
}

// ============================================================================
// split: fp32 -> bf16 hi + lo residual
// ============================================================================
__global__ void split_kernel(const float* __restrict__ src,
                             __nv_bfloat16* __restrict__ hi,
                             __nv_bfloat16* __restrict__ lo, int n4)
{
    int i = blockIdx.x * 256 + threadIdx.x;
    if (i >= n4) return;
    float4 v = ((const float4*)src)[i];
    float f[4] = {v.x, v.y, v.z, v.w};
    __nv_bfloat16 h[4], l[4];
#pragma unroll
    for (int k = 0; k < 4; ++k) {
        h[k] = __float2bfloat16(f[k]);
        l[k] = __float2bfloat16(f[k] - __bfloat162float(h[k]));
    }
    ((__nv_bfloat162*)hi)[2 * i]     = __nv_bfloat162(h[0], h[1]);
    ((__nv_bfloat162*)hi)[2 * i + 1] = __nv_bfloat162(h[2], h[3]);
    ((__nv_bfloat162*)lo)[2 * i]     = __nv_bfloat162(l[0], l[1]);
    ((__nv_bfloat162*)lo)[2 * i + 1] = __nv_bfloat162(l[2], l[3]);
}

// ============================================================================
#define AB_STRIDE 272

// ============================================================================
// Kernel 1: qproj via HMMA 4-term split (unchanged)
// ============================================================================
#define DO_AH 0
#define DO_AL 34816
#define DO_BH 69632
#define DO_BL (69632 + 17408)
#define DO_TOTAL (69632 + 2*17408)   // 104448

__global__ void __launch_bounds__(256, 2) qproj_mma_kernel()
{
    extern __shared__ char smem[];
    const uint32_t smb = smem_u32(smem);
    const int tid  = threadIdx.x;
    const int wid  = tid >> 5;
    const int lane = tid & 31;
    const int m0 = blockIdx.x * 128;
    const int n0 = blockIdx.y * 64;

    const int warp_m = wid >> 1;
    const int warp_n = wid & 1;

    const uint32_t a_row_off = (uint32_t)((warp_m * 32 + (lane & 15)) * AB_STRIDE + (lane >> 4) * 16);
    const uint32_t b_row_off = (uint32_t)((warp_n * 32 + (lane & 7) + ((lane >> 4) << 3)) * AB_STRIDE
                                          + ((lane >> 3) & 1) * 16);

    float C[2][4][4] = {};

    const char* axh = (const char*)(g_xhi + (size_t)m0 * D_DIM);
    const char* axl = (const char*)(g_xlo + (size_t)m0 * D_DIM);
    const char* bh_ = (const char*)(g_wqhi + (size_t)n0 * D_DIM);
    const char* bl_ = (const char*)(g_wqlo + (size_t)n0 * D_DIM);

    for (int kc = 0; kc < D_DIM / 128; ++kc) {
        if (kc) __syncthreads();
        const uint32_t ko = (uint32_t)(kc * 256);
#pragma unroll
        for (int it = 0; it < 8; ++it) {
            int idx = tid + it * 256;
            int r = idx >> 4, seg = idx & 15;
            uint32_t d = (uint32_t)(r * AB_STRIDE + seg * 16);
            uint32_t s = (uint32_t)(r * (D_DIM * 2)) + ko + seg * 16;
            CP_ASYNC16(smb + DO_AH + d, axh + s);
            CP_ASYNC16(smb + DO_AL + d, axl + s);
        }
#pragma unroll
        for (int it = 0; it < 4; ++it) {
            int idx = tid + it * 256;
            int r = idx >> 4, seg = idx & 15;
            uint32_t d = (uint32_t)(r * AB_STRIDE + seg * 16);
            uint32_t s = (uint32_t)(r * (D_DIM * 2)) + ko + seg * 16;
            CP_ASYNC16(smb + DO_BH + d, bh_ + s);
            CP_ASYNC16(smb + DO_BL + d, bl_ + s);
        }
        CP_COMMIT(); CP_WAIT0();
        __syncthreads();

#pragma unroll
        for (int ks = 0; ks < 8; ++ks) {
            const uint32_t koff = (uint32_t)(ks * 32);
            uint32_t bH[8], bL[8];
            ldmx4(bH[0], bH[1], bH[2], bH[3], smb + DO_BH + b_row_off + koff);
            ldmx4(bH[4], bH[5], bH[6], bH[7], smb + DO_BH + b_row_off + koff + 16 * AB_STRIDE);
            ldmx4(bL[0], bL[1], bL[2], bL[3], smb + DO_BL + b_row_off + koff);
            ldmx4(bL[4], bL[5], bL[6], bL[7], smb + DO_BL + b_row_off + koff + 16 * AB_STRIDE);
#pragma unroll
            for (int i = 0; i < 2; ++i) {
                uint32_t ah[4], al[4];
                ldmx4(ah[0], ah[1], ah[2], ah[3],
                      smb + DO_AH + a_row_off + koff + (uint32_t)(i * 16 * AB_STRIDE));
                ldmx4(al[0], al[1], al[2], al[3],
                      smb + DO_AL + a_row_off + koff + (uint32_t)(i * 16 * AB_STRIDE));
#pragma unroll
                for (int j = 0; j < 4; ++j) {
                    mma_bf16(C[i][j], ah, bH + 2 * j);
                    mma_bf16(C[i][j], ah, bL + 2 * j);
                    mma_bf16(C[i][j], al, bH + 2 * j);
                    mma_bf16(C[i][j], al, bL + 2 * j);
                }
            }
        }
    }

    const int trow = lane >> 2;
    const int tcol = (lane & 3) * 2;
#pragma unroll
    for (int i = 0; i < 2; ++i) {
#pragma unroll
        for (int half = 0; half < 2; ++half) {
            int m = m0 + warp_m * 32 + i * 16 + trow + half * 8;
#pragma unroll
            for (int j = 0; j < 4; ++j) {
                int n = n0 + warp_n * 32 + j * 8 + tcol;
                float va = C[i][j][2 * half]     * g_bnA[n]     + g_bnB[n];
                float vb = C[i][j][2 * half + 1] * g_bnA[n + 1] + g_bnB[n + 1];
                *(float2*)(g_qf + (size_t)m * QDIM + n) = make_float2(va, vb);
                *(__nv_bfloat162*)(g_qhi + (size_t)m * QDIM + n) =
                    __nv_bfloat162(__float2bfloat16(va), __float2bfloat16(vb));
            }
        }
    }
}

// ============================================================================
// Kernel 2: pass-1 scores — 512 threads (16 warps 8m x 2n), ONE sync per
// chunk via double-buffered score scratch. GENERIC pointers for sS.
// ============================================================================
#define SMS_A     0            // 128*272 = 34816
#define SMS_B0    34816        // 64*272 = 17408
#define SMS_B1    52224
#define SMS_S0    69632        // float[128][68] = 34816
#define SMS_S1    104448
#define SMS_TOTAL 139264
#define S_STRIDE  68

__global__ void __launch_bounds__(512, 1) scores_mma_kernel()
{
    extern __shared__ char smem[];
    const uint32_t smb = smem_u32(smem);
    const int tid  = threadIdx.x;
    const int wid  = tid >> 5;
    const int lane = tid & 31;

    const int t0 = blockIdx.x * TOK_TILE;
    const int h  = blockIdx.y;
    const int z  = blockIdx.z;
    const int keybase = z * KEYS_PER_SPLIT;

    const int warp_m = wid >> 1;     // 0..7 -> tokens 16*warp_m
    const int warp_n = wid & 1;      // 0..1 -> keys   32*warp_n

    uint32_t bdst[2], bsrc[2];
#pragma unroll
    for (int i = 0; i < 2; ++i) {
        int idx = tid + i * 512;
        int r = idx >> 4, seg = idx & 15;
        bdst[i] = (uint32_t)(r * AB_STRIDE + seg * 16);
        bsrc[i] = (uint32_t)(r * 256 + seg * 16);
    }

    {
        const char* qh = (const char*)(g_qhi + (size_t)t0 * QDIM + h * KD);
#pragma unroll
        for (int i = 0; i < 4; ++i) {
            int idx = tid + i * 512;
            int r = idx >> 4, seg = idx & 15;
            CP_ASYNC16(smb + SMS_A + (uint32_t)(r * AB_STRIDE + seg * 16),
                       qh + (size_t)r * (QDIM * 2) + seg * 16);
        }
    }
    const char* khbase = (const char*)(g_khi + ((size_t)h * N_KEYS + keybase) * KD);
    {
#pragma unroll
        for (int i = 0; i < 2; ++i) CP_ASYNC16(smb + SMS_B0 + bdst[i], khbase + bsrc[i]);
        CP_COMMIT();
    }

    float tv[KNN]; int ti[KNN];
#pragma unroll
    for (int k = 0; k < KNN; ++k) { tv[k] = -FLT_MAX; ti[k] = 0; }
    float minv = -FLT_MAX;

    const uint32_t a_row_off = (uint32_t)((warp_m * 16 + (lane & 15)) * AB_STRIDE + (lane >> 4) * 16);
    const uint32_t b_row_off = (uint32_t)((warp_n * 32 + (lane & 7) + ((lane >> 4) << 3)) * AB_STRIDE
                                          + ((lane >> 3) & 1) * 16);

    float* const sBuf[2] = { (float*)(smem + SMS_S0), (float*)(smem + SMS_S1) };

    const int s_token = tid >> 2;    // 0..127
    const int s_q     = tid & 3;     // 0..3
    const int trow = lane >> 2;
    const int tcol = (lane & 3) * 2;

    for (int c = 0; c < NCHUNK; ++c) {
        const uint32_t bbase = (c & 1) ? (smb + SMS_B1) : (smb + SMS_B0);
        float* scur  = sBuf[c & 1];
        float* sprev = sBuf[(c & 1) ^ 1];

        CP_WAIT0();
        __syncthreads();   // single barrier: B(c) visible; scur's old scan done;
                           // sprev's writes (chunk c-1) visible

        // prefetch B(c+1) — buffer's last reader MMA(c-1) completed before sync
        if (c + 1 < NCHUNK) {
            const uint32_t obase = (c & 1) ? (smb + SMS_B0) : (smb + SMS_B1);
            const uint32_t cb = (uint32_t)((c + 1) * CHUNK_N * KD * 2);
#pragma unroll
            for (int i = 0; i < 2; ++i) CP_ASYNC16(obase + bdst[i], khbase + cb + bsrc[i]);
            CP_COMMIT();
        }

        float C[4][4];
#pragma unroll
        for (int j = 0; j < 4; ++j)
#pragma unroll
            for (int e = 0; e < 4; ++e) C[j][e] = 0.f;

#pragma unroll
        for (int ks = 0; ks < 8; ++ks) {
            const uint32_t koff = (uint32_t)(ks * 32);
            uint32_t bh[8], ah[4];
            ldmx4(bh[0], bh[1], bh[2], bh[3], bbase + b_row_off + koff);
            ldmx4(bh[4], bh[5], bh[6], bh[7], bbase + b_row_off + koff + 16 * AB_STRIDE);
            ldmx4(ah[0], ah[1], ah[2], ah[3], smb + SMS_A + a_row_off + koff);
#pragma unroll
            for (int j = 0; j < 4; ++j) mma_bf16(C[j], ah, bh + 2 * j);
        }

        // write scores of chunk c into scur
        {
            int tok = warp_m * 16 + trow;
#pragma unroll
            for (int j = 0; j < 4; ++j) {
                int key = warp_n * 32 + j * 8 + tcol;
                *(float2*)(scur + (size_t)tok * S_STRIDE + key)       = make_float2(C[j][0], C[j][1]);
                *(float2*)(scur + (size_t)(tok + 8) * S_STRIDE + key) = make_float2(C[j][2], C[j][3]);
            }
        }

        // scan chunk c-1 from sprev (dependency covered by top-of-loop barrier)
        if (c > 0) {
            const float4* row = (const float4*)(sprev + (size_t)s_token * S_STRIDE);
            const int n0 = keybase + (c - 1) * CHUNK_N;
#pragma unroll
            for (int m = 0; m < 4; ++m) {
                int j4 = 4 * m + s_q;
                float4 v = row[j4];
                int base = n0 + 4 * j4;
                if (v.x > minv) { reg_insert16(tv, ti, v.x, base + 0); minv = tv[KNN - 1]; }
                if (v.y > minv) { reg_insert16(tv, ti, v.y, base + 1); minv = tv[KNN - 1]; }
                if (v.z > minv) { reg_insert16(tv, ti, v.z, base + 2); minv = tv[KNN - 1]; }
                if (v.w > minv) { reg_insert16(tv, ti, v.w, base + 3); minv = tv[KNN - 1]; }
            }
        }
    }

    // final chunk's scores still unscanned
    __syncthreads();
    {
        const float* slast = sBuf[(NCHUNK - 1) & 1];
        const float4* row = (const float4*)(slast + (size_t)s_token * S_STRIDE);
        const int n0 = keybase + (NCHUNK - 1) * CHUNK_N;
#pragma unroll
        for (int m = 0; m < 4; ++m) {
            int j4 = 4 * m + s_q;
            float4 v = row[j4];
            int base = n0 + 4 * j4;
            if (v.x > minv) { reg_insert16(tv, ti, v.x, base + 0); minv = tv[KNN - 1]; }
            if (v.y > minv) { reg_insert16(tv, ti, v.y, base + 1); minv = tv[KNN - 1]; }
            if (v.z > minv) { reg_insert16(tv, ti, v.z, base + 2); minv = tv[KNN - 1]; }
            if (v.w > minv) { reg_insert16(tv, ti, v.w, base + 3); minv = tv[KNN - 1]; }
        }
    }

    // merge 4 streams per token (adjacent lanes) via shfl, write top-16 indices
    {
        float ov[KNN]; int oi[KNN];
#pragma unroll
        for (int k = 0; k < KNN; ++k) {
            ov[k] = __shfl_down_sync(0xffffffffu, tv[k], 1);
            oi[k] = __shfl_down_sync(0xffffffffu, ti[k], 1);
        }
        if ((lane & 1) == 0) {
#pragma unroll
            for (int k = 0; k < KNN; ++k)
                if (ov[k] > tv[KNN - 1]) reg_insert16(tv, ti, ov[k], oi[k]);
        }
#pragma unroll
        for (int k = 0; k < KNN; ++k) {
            ov[k] = __shfl_down_sync(0xffffffffu, tv[k], 2);
            oi[k] = __shfl_down_sync(0xffffffffu, ti[k], 2);
        }
        if ((lane & 3) == 0) {
#pragma unroll
            for (int k = 0; k < KNN; ++k)
                if (ov[k] > tv[KNN - 1]) reg_insert16(tv, ti, ov[k], oi[k]);
            size_t pb = (((size_t)(t0 + s_token) * H_HEADS + h) * KEY_SPLITS + z) * KNN;
#pragma unroll
            for (int k = 0; k < KNN; ++k) g_ptopi[pb + k] = ti[k];
        }
    }
}

// ============================================================================
// Kernel 2b: exact fp32 rescore of 64 candidates (unchanged)
// ============================================================================
__global__ void __launch_bounds__(128) rescore_kernel(const float* __restrict__ keys)
{
    const int t = blockIdx.x;
    const int h = threadIdx.x >> 5;
    const int lane = threadIdx.x & 31;
    const int bh = t * H_HEADS + h;

    __shared__ float sq[H_HEADS][KD];
    *(float4*)(&sq[h][lane * 4]) = *(const float4*)(g_qf + (size_t)t * QDIM + h * KD + lane * 4);
    __syncwarp();

    const int idx0 = g_ptopi[(size_t)bh * NCAND + lane];
    const int idx1 = g_ptopi[(size_t)bh * NCAND + 32 + lane];
    const float4* kr0 = (const float4*)(keys + ((size_t)h * N_KEYS + idx0) * KD);
    const float4* kr1 = (const float4*)(keys + ((size_t)h * N_KEYS + idx1) * KD);
    float acc0 = 0.f, acc1 = 0.f;
#pragma unroll
    for (int d4 = 0; d4 < KD / 4; ++d4) {
        float4 k0 = kr0[d4], k1 = kr1[d4];
        float q0 = sq[h][4 * d4 + 0], q1 = sq[h][4 * d4 + 1];
        float q2 = sq[h][4 * d4 + 2], q3 = sq[h][4 * d4 + 3];
        acc0 = fmaf(k0.x, q0, acc0); acc0 = fmaf(k0.y, q1, acc0);
        acc0 = fmaf(k0.z, q2, acc0); acc0 = fmaf(k0.w, q3, acc0);
        acc1 = fmaf(k1.x, q0, acc1); acc1 = fmaf(k1.y, q1, acc1);
        acc1 = fmaf(k1.z, q2, acc1); acc1 = fmaf(k1.w, q3, acc1);
    }

    int rank0 = 0, rank1 = 0;
#pragma unroll
    for (int j = 0; j < 32; ++j) {
        float v0 = __shfl_sync(0xffffffffu, acc0, j);
        float v1 = __shfl_sync(0xffffffffu, acc1, j);
        rank0 += (v0 > acc0) || (v0 == acc0 && j < lane);
        rank0 += (v1 > acc0);
        rank1 += (v0 > acc1) || (v0 == acc1);
        rank1 += (v1 > acc1) || (v1 == acc1 && j < lane);
    }

    float vmax = fmaxf(acc0, acc1);
#pragma unroll
    for (int off = 16; off > 0; off >>= 1)
        vmax = fmaxf(vmax, __shfl_xor_sync(0xffffffffu, vmax, off));
    float e0 = (rank0 < KNN) ? __expf(acc0 - vmax) : 0.f;
    float e1 = (rank1 < KNN) ? __expf(acc1 - vmax) : 0.f;
    float sum = e0 + e1;
#pragma unroll
    for (int off = 16; off > 0; off >>= 1)
        sum += __shfl_xor_sync(0xffffffffu, sum, off);
    float inv = 1.f / sum;
    if (rank0 < KNN) {
        g_gates[(size_t)bh * KNN + rank0]  = e0 * inv;
        g_topidx[(size_t)bh * KNN + rank0] = idx0;
    }
    if (rank1 < KNN) {
        g_gates[(size_t)bh * KNN + rank1]  = e1 * inv;
        g_topidx[(size_t)bh * KNN + rank1] = idx1;
    }
}

// ============================================================================
// Kernel 3: tiny PEER expert network per token (unchanged)
// ============================================================================
__global__ void moe_small_kernel(const float* __restrict__ x,
                                 const float* __restrict__ wdown,
                                 const float* __restrict__ wup,
                                 const float* __restrict__ aw1,
                                 const float* __restrict__ aw2,
                                 const float* __restrict__ aw3)
{
    __shared__ float s_aw1[HID_A * KNN];
    __shared__ float s_aw3[HID_A * KNN];
    __shared__ float s_aw2[KNN * HID_A];
    __shared__ float s_z[H_HEADS][KNN];
    __shared__ float s_hid[H_HEADS][HID_A];
    __shared__ float s_red[H_HEADS];
    __shared__ float s_wred[4];
    __shared__ float s_xsum;

    const int t = blockIdx.x;
    const int tid = threadIdx.x;
    const int w = tid >> 5;
    const int lane = tid & 31;

    for (int i = tid; i < HID_A * KNN; i += 128) { s_aw1[i] = aw1[i]; s_aw3[i] = aw3[i]; s_aw2[i] = aw2[i]; }

    float ps = 0.f;
    for (int i = tid; i < D_DIM; i += 128) ps += x[(size_t)t * D_DIM + i];
#pragma unroll
    for (int off = 16; off > 0; off >>= 1) ps += __shfl_down_sync(0xffffffffu, ps, off);
    if (lane == 0) s_wred[w] = ps;
    __syncthreads();
    if (tid == 0) s_xsum = s_wred[0] + s_wred[1] + s_wred[2] + s_wred[3];
    __syncthreads();
    const float xsum = s_xsum;

    const size_t gbase = ((size_t)t * H_HEADS + w) * KNN;
    if (lane < KNN)
        s_z[w][lane] = xsum * wdown[g_topidx[gbase + lane]];
    __syncwarp();

    for (int a = lane; a < HID_A; a += 32) {
        float d1 = 0.f, d3 = 0.f;
#pragma unroll
        for (int k = 0; k < KNN; ++k) {
            float zz = s_z[w][k];
            d1 = fmaf(zz, s_aw1[a * KNN + k], d1);
            d3 = fmaf(zz, s_aw3[a * KNN + k], d3);
        }
        float sl = d1 / (1.f + __expf(-d1));
        s_hid[w][a] = sl * d3;
    }
    __syncwarp();

    float part = 0.f;
    if (lane < KNN) {
        float o = 0.f;
#pragma unroll
        for (int a = 0; a < HID_A; ++a) o = fmaf(s_hid[w][a], s_aw2[lane * HID_A + a], o);
        int id = g_topidx[gbase + lane];
        part = o * g_gates[gbase + lane] * wup[id];
    }
#pragma unroll
    for (int off = 16; off > 0; off >>= 1) part += __shfl_down_sync(0xffffffffu, part, off);
    if (lane == 0) s_red[w] = part;
    __syncthreads();
    if (tid == 0) g_comb[t] = s_red[0] + s_red[1] + s_red[2] + s_red[3];
}

// ============================================================================
// Kernel 4: swiglu via HMMA 3-term split (unchanged)
// ============================================================================
#define DW_AH 0
#define DW_AL 34816
#define DW_B  69632
#define DW_BSZ 17408
#define DW_TOTAL (DW_B + 4*DW_BSZ)

__global__ void __launch_bounds__(256, 1) swiglu_mma_kernel()
{
    extern __shared__ char smem[];
    const uint32_t smb = smem_u32(smem);
    const int tid  = threadIdx.x;
    const int wid  = tid >> 5;
    const int lane = tid & 31;
    const int m0 = blockIdx.x * 128;
    const int n0 = blockIdx.y * 64;

    const int warp_m = wid >> 1;
    const int warp_n = wid & 1;

    const uint32_t a_row_off = (uint32_t)((warp_m * 32 + (lane & 15)) * AB_STRIDE + (lane >> 4) * 16);
    const uint32_t b_row_off = (uint32_t)((warp_n * 32 + (lane & 7) + ((lane >> 4) << 3)) * AB_STRIDE
                                          + ((lane >> 3) & 1) * 16);

    float C1[2][4][4] = {};
    float C3[2][4][4] = {};

    const char* axh = (const char*)(g_xhi + (size_t)m0 * D_DIM);
    const char* axl = (const char*)(g_xlo + (size_t)m0 * D_DIM);
    const char* b1h = (const char*)(g_w1hi + (size_t)n0 * D_DIM);
    const char* b1l = (const char*)(g_w1lo + (size_t)n0 * D_DIM);
    const char* b3h = (const char*)(g_w3hi + (size_t)n0 * D_DIM);
    const char* b3l = (const char*)(g_w3lo + (size_t)n0 * D_DIM);

    for (int kc = 0; kc < D_DIM / 128; ++kc) {
        if (kc) __syncthreads();
        const uint32_t ko = (uint32_t)(kc * 256);
#pragma unroll
        for (int it = 0; it < 8; ++it) {
            int idx = tid + it * 256;
            int r = idx >> 4, seg = idx & 15;
            uint32_t d = (uint32_t)(r * AB_STRIDE + seg * 16);
            uint32_t s = (uint32_t)(r * (D_DIM * 2)) + ko + seg * 16;
            CP_ASYNC16(smb + DW_AH + d, axh + s);
            CP_ASYNC16(smb + DW_AL + d, axl + s);
        }
#pragma unroll
        for (int it = 0; it < 4; ++it) {
            int idx = tid + it * 256;
            int r = idx >> 4, seg = idx & 15;
            uint32_t d = (uint32_t)(r * AB_STRIDE + seg * 16);
            uint32_t s = (uint32_t)(r * (D_DIM * 2)) + ko + seg * 16;
            CP_ASYNC16(smb + DW_B + 0 * DW_BSZ + d, b1h + s);
            CP_ASYNC16(smb + DW_B + 1 * DW_BSZ + d, b1l + s);
            CP_ASYNC16(smb + DW_B + 2 * DW_BSZ + d, b3h + s);
            CP_ASYNC16(smb + DW_B + 3 * DW_BSZ + d, b3l + s);
        }
        CP_COMMIT(); CP_WAIT0();
        __syncthreads();

#pragma unroll
        for (int ks = 0; ks < 8; ++ks) {
            const uint32_t koff = (uint32_t)(ks * 32);
            uint32_t b1H[8], b1L[8], b3H[8], b3L[8];
            ldmx4(b1H[0], b1H[1], b1H[2], b1H[3], smb + DW_B + 0 * DW_BSZ + b_row_off + koff);
            ldmx4(b1H[4], b1H[5], b1H[6], b1H[7], smb + DW_B + 0 * DW_BSZ + b_row_off + koff + 16 * AB_STRIDE);
            ldmx4(b1L[0], b1L[1], b1L[2], b1L[3], smb + DW_B + 1 * DW_BSZ + b_row_off + koff);
            ldmx4(b1L[4], b1L[5], b1L[6], b1L[7], smb + DW_B + 1 * DW_BSZ + b_row_off + koff + 16 * AB_STRIDE);
            ldmx4(b3H[0], b3H[1], b3H[2], b3H[3], smb + DW_B + 2 * DW_BSZ + b_row_off + koff);
            ldmx4(b3H[4], b3H[5], b3H[6], b3H[7], smb + DW_B + 2 * DW_BSZ + b_row_off + koff + 16 * AB_STRIDE);
            ldmx4(b3L[0], b3L[1], b3L[2], b3L[3], smb + DW_B + 3 * DW_BSZ + b_row_off + koff);
            ldmx4(b3L[4], b3L[5], b3L[6], b3L[7], smb + DW_B + 3 * DW_BSZ + b_row_off + koff + 16 * AB_STRIDE);
#pragma unroll
            for (int i = 0; i < 2; ++i) {
                uint32_t ah[4], al[4];
                ldmx4(ah[0], ah[1], ah[2], ah[3],
                      smb + DW_AH + a_row_off + koff + (uint32_t)(i * 16 * AB_STRIDE));
                ldmx4(al[0], al[1], al[2], al[3],
                      smb + DW_AL + a_row_off + koff + (uint32_t)(i * 16 * AB_STRIDE));
#pragma unroll
                for (int j = 0; j < 4; ++j) {
                    mma_bf16(C1[i][j], ah, b1H + 2 * j);
                    mma_bf16(C1[i][j], ah, b1L + 2 * j);
                    mma_bf16(C1[i][j], al, b1H + 2 * j);
                    mma_bf16(C3[i][j], ah, b3H + 2 * j);
                    mma_bf16(C3[i][j], ah, b3L + 2 * j);
                    mma_bf16(C3[i][j], al, b3H + 2 * j);
                }
            }
        }
    }

    const int trow = lane >> 2;
    const int tcol = (lane & 3) * 2;
#pragma unroll
    for (int i = 0; i < 2; ++i) {
#pragma unroll
        for (int j = 0; j < 4; ++j) {
            int n = n0 + warp_n * 32 + j * 8 + tcol;
#pragma unroll
            for (int half = 0; half < 2; ++half) {
                int m = m0 + warp_m * 32 + i * 16 + trow + half * 8;
                float z1a = C1[i][j][2 * half], z1b = C1[i][j][2 * half + 1];
                float z3a = C3[i][j][2 * half], z3b = C3[i][j][2 * half + 1];
                float va = (z1a / (1.f + __expf(-z1a))) * z3a;
                float vb = (z1b / (1.f + __expf(-z1b))) * z3b;
                __nv_bfloat16 ha = __float2bfloat16(va);
                __nv_bfloat16 hb = __float2bfloat16(vb);
                __nv_bfloat16 la = __float2bfloat16(va - __bfloat162float(ha));
                __nv_bfloat16 lb = __float2bfloat16(vb - __bfloat162float(hb));
                *(__nv_bfloat162*)(g_hidhi + (size_t)m * HID_S + n) = __nv_bfloat162(ha, hb);
                *(__nv_bfloat162*)(g_hidlo + (size_t)m * HID_S + n) = __nv_bfloat162(la, lb);
            }
        }
    }
}

// ============================================================================
// Kernel 5: out = hid @ w2^T + comb (unchanged)
// ============================================================================
__global__ void __launch_bounds__(256, 1) out_mma_kernel(float* __restrict__ out)
{
    extern __shared__ char smem[];
    const uint32_t smb = smem_u32(smem);
    const int tid  = threadIdx.x;
    const int wid  = tid >> 5;
    const int lane = tid & 31;
    const int m0 = blockIdx.x * 128;
    const int n0 = blockIdx.y * 64;

    const int warp_m = wid >> 1;
    const int warp_n = wid & 1;

    const uint32_t a_row_off = (uint32_t)((warp_m * 32 + (lane & 15)) * AB_STRIDE + (lane >> 4) * 16);
    const uint32_t b_row_off = (uint32_t)((warp_n * 32 + (lane & 7) + ((lane >> 4) << 3)) * AB_STRIDE
                                          + ((lane >> 3) & 1) * 16);

    float C[2][4][4] = {};

    const char* axh = (const char*)(g_hidhi + (size_t)m0 * HID_S);
    const char* axl = (const char*)(g_hidlo + (size_t)m0 * HID_S);
    const char* bh_ = (const char*)(g_w2hi + (size_t)n0 * HID_S);
    const char* bl_ = (const char*)(g_w2lo + (size_t)n0 * HID_S);

    for (int kc = 0; kc < HID_S / 128; ++kc) {
        if (kc) __syncthreads();
        const uint32_t ko = (uint32_t)(kc * 256);
#pragma unroll
        for (int it = 0; it < 8; ++it) {
            int idx = tid + it * 256;
            int r = idx >> 4, seg = idx & 15;
            uint32_t d = (uint32_t)(r * AB_STRIDE + seg * 16);
            uint32_t s = (uint32_t)(r * (HID_S * 2)) + ko + seg * 16;
            CP_ASYNC16(smb + DO_AH + d, axh + s);
            CP_ASYNC16(smb + DO_AL + d, axl + s);
        }
#pragma unroll
        for (int it = 0; it < 4; ++it) {
            int idx = tid + it * 256;
            int r = idx >> 4, seg = idx & 15;
            uint32_t d = (uint32_t)(r * AB_STRIDE + seg * 16);
            uint32_t s = (uint32_t)(r * (HID_S * 2)) + ko + seg * 16;
            CP_ASYNC16(smb + DO_BH + d, bh_ + s);
            CP_ASYNC16(smb + DO_BL + d, bl_ + s);
        }
        CP_COMMIT(); CP_WAIT0();
        __syncthreads();

#pragma unroll
        for (int ks = 0; ks < 8; ++ks) {
            const uint32_t koff = (uint32_t)(ks * 32);
            uint32_t bH[8], bL[8];
            ldmx4(bH[0], bH[1], bH[2], bH[3], smb + DO_BH + b_row_off + koff);
            ldmx4(bH[4], bH[5], bH[6], bH[7], smb + DO_BH + b_row_off + koff + 16 * AB_STRIDE);
            ldmx4(bL[0], bL[1], bL[2], bL[3], smb + DO_BL + b_row_off + koff);
            ldmx4(bL[4], bL[5], bL[6], bL[7], smb + DO_BL + b_row_off + koff + 16 * AB_STRIDE);
#pragma unroll
            for (int i = 0; i < 2; ++i) {
                uint32_t ah[4], al[4];
                ldmx4(ah[0], ah[1], ah[2], ah[3],
                      smb + DO_AH + a_row_off + koff + (uint32_t)(i * 16 * AB_STRIDE));
                ldmx4(al[0], al[1], al[2], al[3],
                      smb + DO_AL + a_row_off + koff + (uint32_t)(i * 16 * AB_STRIDE));
#pragma unroll
                for (int j = 0; j < 4; ++j) {
                    mma_bf16(C[i][j], ah, bH + 2 * j);
                    mma_bf16(C[i][j], ah, bL + 2 * j);
                    mma_bf16(C[i][j], al, bH + 2 * j);
                }
            }
        }
    }

    const int trow = lane >> 2;
    const int tcol = (lane & 3) * 2;
#pragma unroll
    for (int i = 0; i < 2; ++i) {
#pragma unroll
        for (int half = 0; half < 2; ++half) {
            int m = m0 + warp_m * 32 + i * 16 + trow + half * 8;
            float cb = g_comb[m];
#pragma unroll
            for (int j = 0; j < 4; ++j) {
                int n = n0 + warp_n * 32 + j * 8 + tcol;
                *(float2*)(out + (size_t)m * D_DIM + n) =
                    make_float2(C[i][j][2 * half] + cb, C[i][j][2 * half + 1] + cb);
            }
        }
    }
}

// ============================================================================
extern "C" void kernel_launch(void* const* d_in, const int* in_sizes, int n_in,
                              void* d_out, int out_size)
{
    const float* x        = (const float*)d_in[0];
    const float* wq       = (const float*)d_in[1];
    const float* bq       = (const float*)d_in[2];
    const float* bn_gamma = (const float*)d_in[3];
    const float* bn_beta  = (const float*)d_in[4];
    const float* bn_mean  = (const float*)d_in[5];
    const float* bn_var   = (const float*)d_in[6];
    const float* keys     = (const float*)d_in[7];
    const float* w_down   = (const float*)d_in[8];
    const float* w_up     = (const float*)d_in[9];
    const float* a_w1     = (const float*)d_in[10];
    const float* a_w2     = (const float*)d_in[11];
    const float* a_w3     = (const float*)d_in[12];
    const float* s_w1     = (const float*)d_in[13];
    const float* s_w2     = (const float*)d_in[14];
    const float* s_w3     = (const float*)d_in[15];
    float* out            = (float*)d_out;

    __nv_bfloat16 *w1hi, *w1lo, *w3hi, *w3lo, *w2hi, *w2lo;
    cudaGetSymbolAddress((void**)&w1hi, g_w1hi); cudaGetSymbolAddress((void**)&w1lo, g_w1lo);
    cudaGetSymbolAddress((void**)&w3hi, g_w3hi); cudaGetSymbolAddress((void**)&w3lo, g_w3lo);
    cudaGetSymbolAddress((void**)&w2hi, g_w2hi); cudaGetSymbolAddress((void**)&w2lo, g_w2lo);

    cudaFuncSetAttribute(scores_mma_kernel,
                         cudaFuncAttributeMaxDynamicSharedMemorySize, SMS_TOTAL);
    cudaFuncSetAttribute(qproj_mma_kernel,
                         cudaFuncAttributeMaxDynamicSharedMemorySize, DO_TOTAL);
    cudaFuncSetAttribute(swiglu_mma_kernel,
                         cudaFuncAttributeMaxDynamicSharedMemorySize, DW_TOTAL);
    cudaFuncSetAttribute(out_mma_kernel,
                         cudaFuncAttributeMaxDynamicSharedMemorySize, DO_TOTAL);

    // launch 1: all pre-qproj prep fused
    prep_all_kernel<<<PREP_TOTAL_BLKS, 256>>>(keys, x, wq, bq, bn_gamma, bn_beta,
                                              bn_mean, bn_var);
    // launch 2
    qproj_mma_kernel<<<dim3(T_TOK / 128, QDIM / 64), 256, DO_TOTAL>>>();
    // launch 3 (independent filler so scores lands at launch 4 for ncu)
    split_kernel<<<(HID_S * D_DIM / 4 + 255) / 256, 256>>>(s_w1, w1hi, w1lo, HID_S * D_DIM / 4);
    // launch 4: the kernel we need profiled
    scores_mma_kernel<<<dim3(T_TOK / TOK_TILE, H_HEADS, KEY_SPLITS), 512, SMS_TOTAL>>>();
    // remaining
    split_kernel<<<(HID_S * D_DIM / 4 + 255) / 256, 256>>>(s_w3, w3hi, w3lo, HID_S * D_DIM / 4);
    split_kernel<<<(D_DIM * HID_S / 4 + 255) / 256, 256>>>(s_w2, w2hi, w2lo, D_DIM * HID_S / 4);
    rescore_kernel<<<T_TOK, 128>>>(keys);
    moe_small_kernel<<<T_TOK, 128>>>(x, w_down, w_up, a_w1, a_w2, a_w3);
    swiglu_mma_kernel<<<dim3(T_TOK / 128, HID_S / 64), 256, DW_TOTAL>>>();
    out_mma_kernel<<<dim3(T_TOK / 128, D_DIM / 64), 256, DO_TOTAL>>>(out);
}

// round 13
// speedup vs baseline: 1.0766x; 1.0766x over previous
#include <cuda_runtime.h>
#include <cuda_bf16.h>
#include <cfloat>
#include <math.h>
#include <cstdint>

#define T_TOK   2048
#define D_DIM   768
#define H_HEADS 4
#define N_KEYS  25600
#define KD      128
#define KNN     16
#define HID_A   44
#define HID_S   1024
#define QDIM    (H_HEADS*KD)   // 512
#define BN_EPS  1e-5f

#define KEY_SPLITS 4
#define KEYS_PER_SPLIT (N_KEYS / KEY_SPLITS)   // 6400
#define CHUNK_N 64
#define NCHUNK (KEYS_PER_SPLIT / CHUNK_N)      // 100
#define TOK_TILE 128
#define NCAND  (KEY_SPLITS * KNN)              // 64 candidates per (token, head)

// ---------------- scratch (device globals; no allocations allowed) ----------
__device__ __nv_bfloat16 g_qhi[T_TOK * QDIM];
__device__ float g_qf[T_TOK * QDIM];
__device__ __nv_bfloat16 g_khi[H_HEADS * N_KEYS * KD];
__device__ int   g_ptopi[T_TOK * H_HEADS * NCAND];
__device__ int   g_topidx[T_TOK * H_HEADS * KNN];
__device__ float g_gates[T_TOK * H_HEADS * KNN];
__device__ float g_comb[T_TOK];
__device__ float g_bnA[QDIM];
__device__ float g_bnB[QDIM];
// bf16 hi/lo operand splits
__device__ __nv_bfloat16 g_xhi[T_TOK * D_DIM];
__device__ __nv_bfloat16 g_xlo[T_TOK * D_DIM];
__device__ __nv_bfloat16 g_wqhi[QDIM * D_DIM];
__device__ __nv_bfloat16 g_wqlo[QDIM * D_DIM];
__device__ __nv_bfloat16 g_w1hi[HID_S * D_DIM];
__device__ __nv_bfloat16 g_w1lo[HID_S * D_DIM];
__device__ __nv_bfloat16 g_w3hi[HID_S * D_DIM];
__device__ __nv_bfloat16 g_w3lo[HID_S * D_DIM];
__device__ __nv_bfloat16 g_w2hi[D_DIM * HID_S];
__device__ __nv_bfloat16 g_w2lo[D_DIM * HID_S];
__device__ __nv_bfloat16 g_hidhi[T_TOK * HID_S];
__device__ __nv_bfloat16 g_hidlo[T_TOK * HID_S];

// ============================================================================
// helpers
// ============================================================================
__device__ __forceinline__ uint32_t smem_u32(const void* p) {
    uint32_t a;
    asm("{ .reg .u64 t; cvta.to.shared.u64 t, %1; cvt.u32.u64 %0, t; }" : "=r"(a) : "l"(p));
    return a;
}
#define CP_ASYNC16(dst, src) \
    asm volatile("cp.async.cg.shared.global [%0], [%1], 16;" :: "r"((uint32_t)(dst)), "l"(src))
#define CP_COMMIT() asm volatile("cp.async.commit_group;" ::: "memory")
#define CP_WAIT0()  asm volatile("cp.async.wait_group 0;" ::: "memory")

__device__ __forceinline__ void ldmx4(uint32_t& r0, uint32_t& r1, uint32_t& r2, uint32_t& r3,
                                      uint32_t addr) {
    asm volatile("ldmatrix.sync.aligned.m8n8.x4.shared.b16 {%0,%1,%2,%3}, [%4];"
                 : "=r"(r0), "=r"(r1), "=r"(r2), "=r"(r3) : "r"(addr));
}
__device__ __forceinline__ void mma_bf16(float* c, const uint32_t* a, const uint32_t* b) {
    asm volatile(
        "mma.sync.aligned.m16n8k16.row.col.f32.bf16.bf16.f32 "
        "{%0,%1,%2,%3}, {%4,%5,%6,%7}, {%8,%9}, {%0,%1,%2,%3};"
        : "+f"(c[0]), "+f"(c[1]), "+f"(c[2]), "+f"(c[3])
        : "r"(a[0]), "r"(a[1]), "r"(a[2]), "r"(a[3]), "r"(b[0]), "r"(b[1]));
}

// fully unrolled register insertion into sorted-desc list of 16
__device__ __forceinline__ void reg_insert16(float* tv, int* ti, float vv, int idx) {
#pragma unroll
    for (int p = KNN - 1; p > 0; --p) {
        bool shift = tv[p - 1] < vv;
        bool here  = !shift && (tv[p] < vv);
        float ntv = shift ? tv[p - 1] : (here ? vv : tv[p]);
        int   nti = shift ? ti[p - 1] : (here ? idx : ti[p]);
        tv[p] = ntv; ti[p] = nti;
    }
    if (tv[0] < vv) { tv[0] = vv; ti[0] = idx; }
}

// ============================================================================
// prep_all: keysprep + split(x) + split(wq) + bnprep in one launch
// ============================================================================
#define PREP_KEY_BLKS ((H_HEADS * N_KEYS * KD) / (256 * 4))
#define PREP_X_BLKS   ((T_TOK * D_DIM) / (256 * 4))
#define PREP_WQ_BLKS  ((QDIM * D_DIM) / (256 * 4))
#define PREP_BN_BLKS  ((QDIM + 255) / 256)
#define PREP_TOTAL_BLKS (PREP_KEY_BLKS + PREP_X_BLKS + PREP_WQ_BLKS + PREP_BN_BLKS)

__global__ void prep_all_kernel(const float* __restrict__ keys,
                                const float* __restrict__ x,
                                const float* __restrict__ wq,
                                const float* __restrict__ bq,
                                const float* __restrict__ gamma,
                                const float* __restrict__ beta,
                                const float* __restrict__ mean,
                                const float* __restrict__ var)
{
    int b = blockIdx.x;
    if (b < PREP_KEY_BLKS) {
        size_t i = (size_t)b * 256 + threadIdx.x;
        const float4 v = ((const float4*)keys)[i];
        ((__nv_bfloat162*)g_khi)[2 * i] =
            __nv_bfloat162(__float2bfloat16(v.x), __float2bfloat16(v.y));
        ((__nv_bfloat162*)g_khi)[2 * i + 1] =
            __nv_bfloat162(__float2bfloat16(v.z), __float2bfloat16(v.w));
        return;
    }
    b -= PREP_KEY_BLKS;
    if (b < PREP_X_BLKS + PREP_WQ_BLKS) {
        const float* src;
        __nv_bfloat16 *hi, *lo;
        size_t i;
        if (b < PREP_X_BLKS) {
            src = x; hi = g_xhi; lo = g_xlo;
            i = (size_t)b * 256 + threadIdx.x;
        } else {
            src = wq; hi = g_wqhi; lo = g_wqlo;
            i = (size_t)(b - PREP_X_BLKS) * 256 + threadIdx.x;
        }
        float4 v = ((const float4*)src)[i];
        float f[4] = {v.x, v.y, v.z, v.w};
        __nv_bfloat16 h[4], l[4];
#pragma unroll
        for (int k = 0; k < 4; ++k) {
            h[k] = __float2bfloat16(f[k]);
            l[k] = __float2bfloat16(f[k] - __bfloat162float(h[k]));
        }
        ((__nv_bfloat162*)hi)[2 * i]     = __nv_bfloat162(h[0], h[1]);
        ((__nv_bfloat162*)hi)[2 * i + 1] = __nv_bfloat162(h[2], h[3]);
        ((__nv_bfloat162*)lo)[2 * i]     = __nv_bfloat162(l[0], l[1]);
        ((__nv_bfloat162*)lo)[2 * i + 1] = __nv_bfloat162(l[2], l[3]);
        return;
    }
    b -= PREP_X_BLKS + PREP_WQ_BLKS;
    {
        int n = b * 256 + threadIdx.x;
        if (n < QDIM) {
            float sc = gamma[n] * rsqrtf(var[n] + BN_EPS);
            g_bnA[n] = sc;
            g_bnB[n] = (bq[n] - mean[n]) * sc + beta[n];
        }
    }
}

// ============================================================================
// split: fp32 -> bf16 hi + lo residual
// ============================================================================
__global__ void split_kernel(const float* __restrict__ src,
                             __nv_bfloat16* __restrict__ hi,
                             __nv_bfloat16* __restrict__ lo, int n4)
{
    int i = blockIdx.x * 256 + threadIdx.x;
    if (i >= n4) return;
    float4 v = ((const float4*)src)[i];
    float f[4] = {v.x, v.y, v.z, v.w};
    __nv_bfloat16 h[4], l[4];
#pragma unroll
    for (int k = 0; k < 4; ++k) {
        h[k] = __float2bfloat16(f[k]);
        l[k] = __float2bfloat16(f[k] - __bfloat162float(h[k]));
    }
    ((__nv_bfloat162*)hi)[2 * i]     = __nv_bfloat162(h[0], h[1]);
    ((__nv_bfloat162*)hi)[2 * i + 1] = __nv_bfloat162(h[2], h[3]);
    ((__nv_bfloat162*)lo)[2 * i]     = __nv_bfloat162(l[0], l[1]);
    ((__nv_bfloat162*)lo)[2 * i + 1] = __nv_bfloat162(l[2], l[3]);
}

// ============================================================================
#define AB_STRIDE 272

// ============================================================================
// Kernel 1: qproj via HMMA 4-term split (unchanged)
// ============================================================================
#define DO_AH 0
#define DO_AL 34816
#define DO_BH 69632
#define DO_BL (69632 + 17408)
#define DO_TOTAL (69632 + 2*17408)   // 104448

__global__ void __launch_bounds__(256, 2) qproj_mma_kernel()
{
    extern __shared__ char smem[];
    const uint32_t smb = smem_u32(smem);
    const int tid  = threadIdx.x;
    const int wid  = tid >> 5;
    const int lane = tid & 31;
    const int m0 = blockIdx.x * 128;
    const int n0 = blockIdx.y * 64;

    const int warp_m = wid >> 1;
    const int warp_n = wid & 1;

    const uint32_t a_row_off = (uint32_t)((warp_m * 32 + (lane & 15)) * AB_STRIDE + (lane >> 4) * 16);
    const uint32_t b_row_off = (uint32_t)((warp_n * 32 + (lane & 7) + ((lane >> 4) << 3)) * AB_STRIDE
                                          + ((lane >> 3) & 1) * 16);

    float C[2][4][4] = {};

    const char* axh = (const char*)(g_xhi + (size_t)m0 * D_DIM);
    const char* axl = (const char*)(g_xlo + (size_t)m0 * D_DIM);
    const char* bh_ = (const char*)(g_wqhi + (size_t)n0 * D_DIM);
    const char* bl_ = (const char*)(g_wqlo + (size_t)n0 * D_DIM);

    for (int kc = 0; kc < D_DIM / 128; ++kc) {
        if (kc) __syncthreads();
        const uint32_t ko = (uint32_t)(kc * 256);
#pragma unroll
        for (int it = 0; it < 8; ++it) {
            int idx = tid + it * 256;
            int r = idx >> 4, seg = idx & 15;
            uint32_t d = (uint32_t)(r * AB_STRIDE + seg * 16);
            uint32_t s = (uint32_t)(r * (D_DIM * 2)) + ko + seg * 16;
            CP_ASYNC16(smb + DO_AH + d, axh + s);
            CP_ASYNC16(smb + DO_AL + d, axl + s);
        }
#pragma unroll
        for (int it = 0; it < 4; ++it) {
            int idx = tid + it * 256;
            int r = idx >> 4, seg = idx & 15;
            uint32_t d = (uint32_t)(r * AB_STRIDE + seg * 16);
            uint32_t s = (uint32_t)(r * (D_DIM * 2)) + ko + seg * 16;
            CP_ASYNC16(smb + DO_BH + d, bh_ + s);
            CP_ASYNC16(smb + DO_BL + d, bl_ + s);
        }
        CP_COMMIT(); CP_WAIT0();
        __syncthreads();

#pragma unroll
        for (int ks = 0; ks < 8; ++ks) {
            const uint32_t koff = (uint32_t)(ks * 32);
            uint32_t bH[8], bL[8];
            ldmx4(bH[0], bH[1], bH[2], bH[3], smb + DO_BH + b_row_off + koff);
            ldmx4(bH[4], bH[5], bH[6], bH[7], smb + DO_BH + b_row_off + koff + 16 * AB_STRIDE);
            ldmx4(bL[0], bL[1], bL[2], bL[3], smb + DO_BL + b_row_off + koff);
            ldmx4(bL[4], bL[5], bL[6], bL[7], smb + DO_BL + b_row_off + koff + 16 * AB_STRIDE);
#pragma unroll
            for (int i = 0; i < 2; ++i) {
                uint32_t ah[4], al[4];
                ldmx4(ah[0], ah[1], ah[2], ah[3],
                      smb + DO_AH + a_row_off + koff + (uint32_t)(i * 16 * AB_STRIDE));
                ldmx4(al[0], al[1], al[2], al[3],
                      smb + DO_AL + a_row_off + koff + (uint32_t)(i * 16 * AB_STRIDE));
#pragma unroll
                for (int j = 0; j < 4; ++j) {
                    mma_bf16(C[i][j], ah, bH + 2 * j);
                    mma_bf16(C[i][j], ah, bL + 2 * j);
                    mma_bf16(C[i][j], al, bH + 2 * j);
                    mma_bf16(C[i][j], al, bL + 2 * j);
                }
            }
        }
    }

    const int trow = lane >> 2;
    const int tcol = (lane & 3) * 2;
#pragma unroll
    for (int i = 0; i < 2; ++i) {
#pragma unroll
        for (int half = 0; half < 2; ++half) {
            int m = m0 + warp_m * 32 + i * 16 + trow + half * 8;
#pragma unroll
            for (int j = 0; j < 4; ++j) {
                int n = n0 + warp_n * 32 + j * 8 + tcol;
                float va = C[i][j][2 * half]     * g_bnA[n]     + g_bnB[n];
                float vb = C[i][j][2 * half + 1] * g_bnA[n + 1] + g_bnB[n + 1];
                *(float2*)(g_qf + (size_t)m * QDIM + n) = make_float2(va, vb);
                *(__nv_bfloat162*)(g_qhi + (size_t)m * QDIM + n) =
                    __nv_bfloat162(__float2bfloat16(va), __float2bfloat16(vb));
            }
        }
    }
}

// ============================================================================
// Kernel 2: pass-1 scores — REGISTER-RESIDENT top-k scan (no score smem).
// 256 threads, 8 warps, warp tile 16 tokens x 64 keys. 2 CTAs/SM, 1 wave.
// Each lane owns two token streams (trow, trow+8), scans its own fragments.
// ============================================================================
#define SMS_A     0            // 128*272 = 34816
#define SMS_B0    34816        // 64*272 = 17408
#define SMS_B1    52224
#define SMS_TOTAL 69632

__global__ void __launch_bounds__(256, 2) scores_mma_kernel()
{
    extern __shared__ char smem[];
    const uint32_t smb = smem_u32(smem);
    const int tid  = threadIdx.x;
    const int wid  = tid >> 5;       // 0..7 -> tokens 16*wid
    const int lane = tid & 31;

    const int t0 = blockIdx.x * TOK_TILE;
    const int h  = blockIdx.y;
    const int z  = blockIdx.z;
    const int keybase = z * KEYS_PER_SPLIT;

    // B staging: 64 rows x 16 segs = 1024 tasks / 256 thr = 4 each
    uint32_t bdst[4], bsrc[4];
#pragma unroll
    for (int i = 0; i < 4; ++i) {
        int idx = tid + i * 256;
        int r = idx >> 4, seg = idx & 15;
        bdst[i] = (uint32_t)(r * AB_STRIDE + seg * 16);
        bsrc[i] = (uint32_t)(r * 256 + seg * 16);
    }

    // stage A (q hi, 128 rows x 16 segs = 8 each) + first B chunk
    {
        const char* qh = (const char*)(g_qhi + (size_t)t0 * QDIM + h * KD);
#pragma unroll
        for (int i = 0; i < 8; ++i) {
            int idx = tid + i * 256;
            int r = idx >> 4, seg = idx & 15;
            CP_ASYNC16(smb + SMS_A + (uint32_t)(r * AB_STRIDE + seg * 16),
                       qh + (size_t)r * (QDIM * 2) + seg * 16);
        }
    }
    const char* khbase = (const char*)(g_khi + ((size_t)h * N_KEYS + keybase) * KD);
    {
#pragma unroll
        for (int i = 0; i < 4; ++i) CP_ASYNC16(smb + SMS_B0 + bdst[i], khbase + bsrc[i]);
        CP_COMMIT();
    }

    // two register top-16 lists per lane: token rows trow and trow+8
    float tvA[KNN], tvB[KNN];
    int   tiA[KNN], tiB[KNN];
#pragma unroll
    for (int k = 0; k < KNN; ++k) {
        tvA[k] = -FLT_MAX; tvB[k] = -FLT_MAX; tiA[k] = 0; tiB[k] = 0;
    }
    float minvA = -FLT_MAX, minvB = -FLT_MAX;

    const uint32_t a_row_off = (uint32_t)((wid * 16 + (lane & 15)) * AB_STRIDE + (lane >> 4) * 16);
    const uint32_t b_row_off = (uint32_t)(((lane & 7) + ((lane >> 4) << 3)) * AB_STRIDE
                                          + ((lane >> 3) & 1) * 16);

    const int tcol = (lane & 3) * 2;

    for (int c = 0; c < NCHUNK; ++c) {
        const uint32_t bbase = (c & 1) ? (smb + SMS_B1) : (smb + SMS_B0);
        CP_WAIT0();
        __syncthreads();   // B(c) staged; MMA(c-1) done with other buffer

        // prefetch B(c+1) into other buffer (overlaps MMA)
        if (c + 1 < NCHUNK) {
            const uint32_t obase = (c & 1) ? (smb + SMS_B0) : (smb + SMS_B1);
            const uint32_t cb = (uint32_t)((c + 1) * CHUNK_N * KD * 2);
#pragma unroll
            for (int i = 0; i < 4; ++i) CP_ASYNC16(obase + bdst[i], khbase + cb + bsrc[i]);
            CP_COMMIT();
        }

        float C[8][4];
#pragma unroll
        for (int j = 0; j < 8; ++j)
#pragma unroll
            for (int e = 0; e < 4; ++e) C[j][e] = 0.f;

#pragma unroll
        for (int ks = 0; ks < 8; ++ks) {
            const uint32_t koff = (uint32_t)(ks * 32);
            uint32_t bh[16], ah[4];
            ldmx4(bh[0],  bh[1],  bh[2],  bh[3],  bbase + b_row_off + koff);
            ldmx4(bh[4],  bh[5],  bh[6],  bh[7],  bbase + b_row_off + koff + 16 * AB_STRIDE);
            ldmx4(bh[8],  bh[9],  bh[10], bh[11], bbase + b_row_off + koff + 32 * AB_STRIDE);
            ldmx4(bh[12], bh[13], bh[14], bh[15], bbase + b_row_off + koff + 48 * AB_STRIDE);
            ldmx4(ah[0], ah[1], ah[2], ah[3], smb + SMS_A + a_row_off + koff);
#pragma unroll
            for (int j = 0; j < 8; ++j) mma_bf16(C[j], ah, bh + 2 * j);
        }

        // register-resident scan: token row A gets C[j][0..1], row B gets C[j][2..3]
        const int kb = keybase + c * CHUNK_N + tcol;
#pragma unroll
        for (int j = 0; j < 8; ++j) {
            float v0 = C[j][0], v1 = C[j][1];
            if (v0 > minvA) { reg_insert16(tvA, tiA, v0, kb + j * 8);     minvA = tvA[KNN - 1]; }
            if (v1 > minvA) { reg_insert16(tvA, tiA, v1, kb + j * 8 + 1); minvA = tvA[KNN - 1]; }
            float v2 = C[j][2], v3 = C[j][3];
            if (v2 > minvB) { reg_insert16(tvB, tiB, v2, kb + j * 8);     minvB = tvB[KNN - 1]; }
            if (v3 > minvB) { reg_insert16(tvB, tiB, v3, kb + j * 8 + 1); minvB = tvB[KNN - 1]; }
        }
    }

    // merge the 4 lanes of each trow group (lanes 4t..4t+3) via shfl
    {
        float ov[KNN]; int oi[KNN];
        // ---- list A ----
#pragma unroll
        for (int k = 0; k < KNN; ++k) {
            ov[k] = __shfl_down_sync(0xffffffffu, tvA[k], 1);
            oi[k] = __shfl_down_sync(0xffffffffu, tiA[k], 1);
        }
        if ((lane & 1) == 0) {
#pragma unroll
            for (int k = 0; k < KNN; ++k)
                if (ov[k] > tvA[KNN - 1]) reg_insert16(tvA, tiA, ov[k], oi[k]);
        }
#pragma unroll
        for (int k = 0; k < KNN; ++k) {
            ov[k] = __shfl_down_sync(0xffffffffu, tvA[k], 2);
            oi[k] = __shfl_down_sync(0xffffffffu, tiA[k], 2);
        }
        if ((lane & 3) == 0) {
#pragma unroll
            for (int k = 0; k < KNN; ++k)
                if (ov[k] > tvA[KNN - 1]) reg_insert16(tvA, tiA, ov[k], oi[k]);
        }
        // ---- list B ----
#pragma unroll
        for (int k = 0; k < KNN; ++k) {
            ov[k] = __shfl_down_sync(0xffffffffu, tvB[k], 1);
            oi[k] = __shfl_down_sync(0xffffffffu, tiB[k], 1);
        }
        if ((lane & 1) == 0) {
#pragma unroll
            for (int k = 0; k < KNN; ++k)
                if (ov[k] > tvB[KNN - 1]) reg_insert16(tvB, tiB, ov[k], oi[k]);
        }
#pragma unroll
        for (int k = 0; k < KNN; ++k) {
            ov[k] = __shfl_down_sync(0xffffffffu, tvB[k], 2);
            oi[k] = __shfl_down_sync(0xffffffffu, tiB[k], 2);
        }
        if ((lane & 3) == 0) {
#pragma unroll
            for (int k = 0; k < KNN; ++k)
                if (ov[k] > tvB[KNN - 1]) reg_insert16(tvB, tiB, ov[k], oi[k]);
            // write both token rows' candidate lists
            int tA = t0 + wid * 16 + (lane >> 2);
            int tB = tA + 8;
            size_t pbA = (((size_t)tA * H_HEADS + h) * KEY_SPLITS + z) * KNN;
            size_t pbB = (((size_t)tB * H_HEADS + h) * KEY_SPLITS + z) * KNN;
#pragma unroll
            for (int k = 0; k < KNN; ++k) {
                g_ptopi[pbA + k] = tiA[k];
                g_ptopi[pbB + k] = tiB[k];
            }
        }
    }
}

// ============================================================================
// Kernel 2b: exact fp32 rescore of 64 candidates (unchanged)
// ============================================================================
__global__ void __launch_bounds__(128) rescore_kernel(const float* __restrict__ keys)
{
    const int t = blockIdx.x;
    const int h = threadIdx.x >> 5;
    const int lane = threadIdx.x & 31;
    const int bh = t * H_HEADS + h;

    __shared__ float sq[H_HEADS][KD];
    *(float4*)(&sq[h][lane * 4]) = *(const float4*)(g_qf + (size_t)t * QDIM + h * KD + lane * 4);
    __syncwarp();

    const int idx0 = g_ptopi[(size_t)bh * NCAND + lane];
    const int idx1 = g_ptopi[(size_t)bh * NCAND + 32 + lane];
    const float4* kr0 = (const float4*)(keys + ((size_t)h * N_KEYS + idx0) * KD);
    const float4* kr1 = (const float4*)(keys + ((size_t)h * N_KEYS + idx1) * KD);
    float acc0 = 0.f, acc1 = 0.f;
#pragma unroll
    for (int d4 = 0; d4 < KD / 4; ++d4) {
        float4 k0 = kr0[d4], k1 = kr1[d4];
        float q0 = sq[h][4 * d4 + 0], q1 = sq[h][4 * d4 + 1];
        float q2 = sq[h][4 * d4 + 2], q3 = sq[h][4 * d4 + 3];
        acc0 = fmaf(k0.x, q0, acc0); acc0 = fmaf(k0.y, q1, acc0);
        acc0 = fmaf(k0.z, q2, acc0); acc0 = fmaf(k0.w, q3, acc0);
        acc1 = fmaf(k1.x, q0, acc1); acc1 = fmaf(k1.y, q1, acc1);
        acc1 = fmaf(k1.z, q2, acc1); acc1 = fmaf(k1.w, q3, acc1);
    }

    int rank0 = 0, rank1 = 0;
#pragma unroll
    for (int j = 0; j < 32; ++j) {
        float v0 = __shfl_sync(0xffffffffu, acc0, j);
        float v1 = __shfl_sync(0xffffffffu, acc1, j);
        rank0 += (v0 > acc0) || (v0 == acc0 && j < lane);
        rank0 += (v1 > acc0);
        rank1 += (v0 > acc1) || (v0 == acc1);
        rank1 += (v1 > acc1) || (v1 == acc1 && j < lane);
    }

    float vmax = fmaxf(acc0, acc1);
#pragma unroll
    for (int off = 16; off > 0; off >>= 1)
        vmax = fmaxf(vmax, __shfl_xor_sync(0xffffffffu, vmax, off));
    float e0 = (rank0 < KNN) ? __expf(acc0 - vmax) : 0.f;
    float e1 = (rank1 < KNN) ? __expf(acc1 - vmax) : 0.f;
    float sum = e0 + e1;
#pragma unroll
    for (int off = 16; off > 0; off >>= 1)
        sum += __shfl_xor_sync(0xffffffffu, sum, off);
    float inv = 1.f / sum;
    if (rank0 < KNN) {
        g_gates[(size_t)bh * KNN + rank0]  = e0 * inv;
        g_topidx[(size_t)bh * KNN + rank0] = idx0;
    }
    if (rank1 < KNN) {
        g_gates[(size_t)bh * KNN + rank1]  = e1 * inv;
        g_topidx[(size_t)bh * KNN + rank1] = idx1;
    }
}

// ============================================================================
// Kernel 3: tiny PEER expert network per token (unchanged)
// ============================================================================
__global__ void moe_small_kernel(const float* __restrict__ x,
                                 const float* __restrict__ wdown,
                                 const float* __restrict__ wup,
                                 const float* __restrict__ aw1,
                                 const float* __restrict__ aw2,
                                 const float* __restrict__ aw3)
{
    __shared__ float s_aw1[HID_A * KNN];
    __shared__ float s_aw3[HID_A * KNN];
    __shared__ float s_aw2[KNN * HID_A];
    __shared__ float s_z[H_HEADS][KNN];
    __shared__ float s_hid[H_HEADS][HID_A];
    __shared__ float s_red[H_HEADS];
    __shared__ float s_wred[4];
    __shared__ float s_xsum;

    const int t = blockIdx.x;
    const int tid = threadIdx.x;
    const int w = tid >> 5;
    const int lane = tid & 31;

    for (int i = tid; i < HID_A * KNN; i += 128) { s_aw1[i] = aw1[i]; s_aw3[i] = aw3[i]; s_aw2[i] = aw2[i]; }

    float ps = 0.f;
    for (int i = tid; i < D_DIM; i += 128) ps += x[(size_t)t * D_DIM + i];
#pragma unroll
    for (int off = 16; off > 0; off >>= 1) ps += __shfl_down_sync(0xffffffffu, ps, off);
    if (lane == 0) s_wred[w] = ps;
    __syncthreads();
    if (tid == 0) s_xsum = s_wred[0] + s_wred[1] + s_wred[2] + s_wred[3];
    __syncthreads();
    const float xsum = s_xsum;

    const size_t gbase = ((size_t)t * H_HEADS + w) * KNN;
    if (lane < KNN)
        s_z[w][lane] = xsum * wdown[g_topidx[gbase + lane]];
    __syncwarp();

    for (int a = lane; a < HID_A; a += 32) {
        float d1 = 0.f, d3 = 0.f;
#pragma unroll
        for (int k = 0; k < KNN; ++k) {
            float zz = s_z[w][k];
            d1 = fmaf(zz, s_aw1[a * KNN + k], d1);
            d3 = fmaf(zz, s_aw3[a * KNN + k], d3);
        }
        float sl = d1 / (1.f + __expf(-d1));
        s_hid[w][a] = sl * d3;
    }
    __syncwarp();

    float part = 0.f;
    if (lane < KNN) {
        float o = 0.f;
#pragma unroll
        for (int a = 0; a < HID_A; ++a) o = fmaf(s_hid[w][a], s_aw2[lane * HID_A + a], o);
        int id = g_topidx[gbase + lane];
        part = o * g_gates[gbase + lane] * wup[id];
    }
#pragma unroll
    for (int off = 16; off > 0; off >>= 1) part += __shfl_down_sync(0xffffffffu, part, off);
    if (lane == 0) s_red[w] = part;
    __syncthreads();
    if (tid == 0) g_comb[t] = s_red[0] + s_red[1] + s_red[2] + s_red[3];
}

// ============================================================================
// Kernel 4: swiglu via HMMA 3-term split (unchanged)
// ============================================================================
#define DW_AH 0
#define DW_AL 34816
#define DW_B  69632
#define DW_BSZ 17408
#define DW_TOTAL (DW_B + 4*DW_BSZ)

__global__ void __launch_bounds__(256, 1) swiglu_mma_kernel()
{
    extern __shared__ char smem[];
    const uint32_t smb = smem_u32(smem);
    const int tid  = threadIdx.x;
    const int wid  = tid >> 5;
    const int lane = tid & 31;
    const int m0 = blockIdx.x * 128;
    const int n0 = blockIdx.y * 64;

    const int warp_m = wid >> 1;
    const int warp_n = wid & 1;

    const uint32_t a_row_off = (uint32_t)((warp_m * 32 + (lane & 15)) * AB_STRIDE + (lane >> 4) * 16);
    const uint32_t b_row_off = (uint32_t)((warp_n * 32 + (lane & 7) + ((lane >> 4) << 3)) * AB_STRIDE
                                          + ((lane >> 3) & 1) * 16);

    float C1[2][4][4] = {};
    float C3[2][4][4] = {};

    const char* axh = (const char*)(g_xhi + (size_t)m0 * D_DIM);
    const char* axl = (const char*)(g_xlo + (size_t)m0 * D_DIM);
    const char* b1h = (const char*)(g_w1hi + (size_t)n0 * D_DIM);
    const char* b1l = (const char*)(g_w1lo + (size_t)n0 * D_DIM);
    const char* b3h = (const char*)(g_w3hi + (size_t)n0 * D_DIM);
    const char* b3l = (const char*)(g_w3lo + (size_t)n0 * D_DIM);

    for (int kc = 0; kc < D_DIM / 128; ++kc) {
        if (kc) __syncthreads();
        const uint32_t ko = (uint32_t)(kc * 256);
#pragma unroll
        for (int it = 0; it < 8; ++it) {
            int idx = tid + it * 256;
            int r = idx >> 4, seg = idx & 15;
            uint32_t d = (uint32_t)(r * AB_STRIDE + seg * 16);
            uint32_t s = (uint32_t)(r * (D_DIM * 2)) + ko + seg * 16;
            CP_ASYNC16(smb + DW_AH + d, axh + s);
            CP_ASYNC16(smb + DW_AL + d, axl + s);
        }
#pragma unroll
        for (int it = 0; it < 4; ++it) {
            int idx = tid + it * 256;
            int r = idx >> 4, seg = idx & 15;
            uint32_t d = (uint32_t)(r * AB_STRIDE + seg * 16);
            uint32_t s = (uint32_t)(r * (D_DIM * 2)) + ko + seg * 16;
            CP_ASYNC16(smb + DW_B + 0 * DW_BSZ + d, b1h + s);
            CP_ASYNC16(smb + DW_B + 1 * DW_BSZ + d, b1l + s);
            CP_ASYNC16(smb + DW_B + 2 * DW_BSZ + d, b3h + s);
            CP_ASYNC16(smb + DW_B + 3 * DW_BSZ + d, b3l + s);
        }
        CP_COMMIT(); CP_WAIT0();
        __syncthreads();

#pragma unroll
        for (int ks = 0; ks < 8; ++ks) {
            const uint32_t koff = (uint32_t)(ks * 32);
            uint32_t b1H[8], b1L[8], b3H[8], b3L[8];
            ldmx4(b1H[0], b1H[1], b1H[2], b1H[3], smb + DW_B + 0 * DW_BSZ + b_row_off + koff);
            ldmx4(b1H[4], b1H[5], b1H[6], b1H[7], smb + DW_B + 0 * DW_BSZ + b_row_off + koff + 16 * AB_STRIDE);
            ldmx4(b1L[0], b1L[1], b1L[2], b1L[3], smb + DW_B + 1 * DW_BSZ + b_row_off + koff);
            ldmx4(b1L[4], b1L[5], b1L[6], b1L[7], smb + DW_B + 1 * DW_BSZ + b_row_off + koff + 16 * AB_STRIDE);
            ldmx4(b3H[0], b3H[1], b3H[2], b3H[3], smb + DW_B + 2 * DW_BSZ + b_row_off + koff);
            ldmx4(b3H[4], b3H[5], b3H[6], b3H[7], smb + DW_B + 2 * DW_BSZ + b_row_off + koff + 16 * AB_STRIDE);
            ldmx4(b3L[0], b3L[1], b3L[2], b3L[3], smb + DW_B + 3 * DW_BSZ + b_row_off + koff);
            ldmx4(b3L[4], b3L[5], b3L[6], b3L[7], smb + DW_B + 3 * DW_BSZ + b_row_off + koff + 16 * AB_STRIDE);
#pragma unroll
            for (int i = 0; i < 2; ++i) {
                uint32_t ah[4], al[4];
                ldmx4(ah[0], ah[1], ah[2], ah[3],
                      smb + DW_AH + a_row_off + koff + (uint32_t)(i * 16 * AB_STRIDE));
                ldmx4(al[0], al[1], al[2], al[3],
                      smb + DW_AL + a_row_off + koff + (uint32_t)(i * 16 * AB_STRIDE));
#pragma unroll
                for (int j = 0; j < 4; ++j) {
                    mma_bf16(C1[i][j], ah, b1H + 2 * j);
                    mma_bf16(C1[i][j], ah, b1L + 2 * j);
                    mma_bf16(C1[i][j], al, b1H + 2 * j);
                    mma_bf16(C3[i][j], ah, b3H + 2 * j);
                    mma_bf16(C3[i][j], ah, b3L + 2 * j);
                    mma_bf16(C3[i][j], al, b3H + 2 * j);
                }
            }
        }
    }

    const int trow = lane >> 2;
    const int tcol = (lane & 3) * 2;
#pragma unroll
    for (int i = 0; i < 2; ++i) {
#pragma unroll
        for (int j = 0; j < 4; ++j) {
            int n = n0 + warp_n * 32 + j * 8 + tcol;
#pragma unroll
            for (int half = 0; half < 2; ++half) {
                int m = m0 + warp_m * 32 + i * 16 + trow + half * 8;
                float z1a = C1[i][j][2 * half], z1b = C1[i][j][2 * half + 1];
                float z3a = C3[i][j][2 * half], z3b = C3[i][j][2 * half + 1];
                float va = (z1a / (1.f + __expf(-z1a))) * z3a;
                float vb = (z1b / (1.f + __expf(-z1b))) * z3b;
                __nv_bfloat16 ha = __float2bfloat16(va);
                __nv_bfloat16 hb = __float2bfloat16(vb);
                __nv_bfloat16 la = __float2bfloat16(va - __bfloat162float(ha));
                __nv_bfloat16 lb = __float2bfloat16(vb - __bfloat162float(hb));
                *(__nv_bfloat162*)(g_hidhi + (size_t)m * HID_S + n) = __nv_bfloat162(ha, hb);
                *(__nv_bfloat162*)(g_hidlo + (size_t)m * HID_S + n) = __nv_bfloat162(la, lb);
            }
        }
    }
}

// ============================================================================
// Kernel 5: out = hid @ w2^T + comb (unchanged)
// ============================================================================
__global__ void __launch_bounds__(256, 1) out_mma_kernel(float* __restrict__ out)
{
    extern __shared__ char smem[];
    const uint32_t smb = smem_u32(smem);
    const int tid  = threadIdx.x;
    const int wid  = tid >> 5;
    const int lane = tid & 31;
    const int m0 = blockIdx.x * 128;
    const int n0 = blockIdx.y * 64;

    const int warp_m = wid >> 1;
    const int warp_n = wid & 1;

    const uint32_t a_row_off = (uint32_t)((warp_m * 32 + (lane & 15)) * AB_STRIDE + (lane >> 4) * 16);
    const uint32_t b_row_off = (uint32_t)((warp_n * 32 + (lane & 7) + ((lane >> 4) << 3)) * AB_STRIDE
                                          + ((lane >> 3) & 1) * 16);

    float C[2][4][4] = {};

    const char* axh = (const char*)(g_hidhi + (size_t)m0 * HID_S);
    const char* axl = (const char*)(g_hidlo + (size_t)m0 * HID_S);
    const char* bh_ = (const char*)(g_w2hi + (size_t)n0 * HID_S);
    const char* bl_ = (const char*)(g_w2lo + (size_t)n0 * HID_S);

    for (int kc = 0; kc < HID_S / 128; ++kc) {
        if (kc) __syncthreads();
        const uint32_t ko = (uint32_t)(kc * 256);
#pragma unroll
        for (int it = 0; it < 8; ++it) {
            int idx = tid + it * 256;
            int r = idx >> 4, seg = idx & 15;
            uint32_t d = (uint32_t)(r * AB_STRIDE + seg * 16);
            uint32_t s = (uint32_t)(r * (HID_S * 2)) + ko + seg * 16;
            CP_ASYNC16(smb + DO_AH + d, axh + s);
            CP_ASYNC16(smb + DO_AL + d, axl + s);
        }
#pragma unroll
        for (int it = 0; it < 4; ++it) {
            int idx = tid + it * 256;
            int r = idx >> 4, seg = idx & 15;
            uint32_t d = (uint32_t)(r * AB_STRIDE + seg * 16);
            uint32_t s = (uint32_t)(r * (HID_S * 2)) + ko + seg * 16;
            CP_ASYNC16(smb + DO_BH + d, bh_ + s);
            CP_ASYNC16(smb + DO_BL + d, bl_ + s);
        }
        CP_COMMIT(); CP_WAIT0();
        __syncthreads();

#pragma unroll
        for (int ks = 0; ks < 8; ++ks) {
            const uint32_t koff = (uint32_t)(ks * 32);
            uint32_t bH[8], bL[8];
            ldmx4(bH[0], bH[1], bH[2], bH[3], smb + DO_BH + b_row_off + koff);
            ldmx4(bH[4], bH[5], bH[6], bH[7], smb + DO_BH + b_row_off + koff + 16 * AB_STRIDE);
            ldmx4(bL[0], bL[1], bL[2], bL[3], smb + DO_BL + b_row_off + koff);
            ldmx4(bL[4], bL[5], bL[6], bL[7], smb + DO_BL + b_row_off + koff + 16 * AB_STRIDE);
#pragma unroll
            for (int i = 0; i < 2; ++i) {
                uint32_t ah[4], al[4];
                ldmx4(ah[0], ah[1], ah[2], ah[3],
                      smb + DO_AH + a_row_off + koff + (uint32_t)(i * 16 * AB_STRIDE));
                ldmx4(al[0], al[1], al[2], al[3],
                      smb + DO_AL + a_row_off + koff + (uint32_t)(i * 16 * AB_STRIDE));
#pragma unroll
                for (int j = 0; j < 4; ++j) {
                    mma_bf16(C[i][j], ah, bH + 2 * j);
                    mma_bf16(C[i][j], ah, bL + 2 * j);
                    mma_bf16(C[i][j], al, bH + 2 * j);
                }
            }
        }
    }

    const int trow = lane >> 2;
    const int tcol = (lane & 3) * 2;
#pragma unroll
    for (int i = 0; i < 2; ++i) {
#pragma unroll
        for (int half = 0; half < 2; ++half) {
            int m = m0 + warp_m * 32 + i * 16 + trow + half * 8;
            float cb = g_comb[m];
#pragma unroll
            for (int j = 0; j < 4; ++j) {
                int n = n0 + warp_n * 32 + j * 8 + tcol;
                *(float2*)(out + (size_t)m * D_DIM + n) =
                    make_float2(C[i][j][2 * half] + cb, C[i][j][2 * half + 1] + cb);
            }
        }
    }
}

// ============================================================================
extern "C" void kernel_launch(void* const* d_in, const int* in_sizes, int n_in,
                              void* d_out, int out_size)
{
    const float* x        = (const float*)d_in[0];
    const float* wq       = (const float*)d_in[1];
    const float* bq       = (const float*)d_in[2];
    const float* bn_gamma = (const float*)d_in[3];
    const float* bn_beta  = (const float*)d_in[4];
    const float* bn_mean  = (const float*)d_in[5];
    const float* bn_var   = (const float*)d_in[6];
    const float* keys     = (const float*)d_in[7];
    const float* w_down   = (const float*)d_in[8];
    const float* w_up     = (const float*)d_in[9];
    const float* a_w1     = (const float*)d_in[10];
    const float* a_w2     = (const float*)d_in[11];
    const float* a_w3     = (const float*)d_in[12];
    const float* s_w1     = (const float*)d_in[13];
    const float* s_w2     = (const float*)d_in[14];
    const float* s_w3     = (const float*)d_in[15];
    float* out            = (float*)d_out;

    __nv_bfloat16 *w1hi, *w1lo, *w3hi, *w3lo, *w2hi, *w2lo;
    cudaGetSymbolAddress((void**)&w1hi, g_w1hi); cudaGetSymbolAddress((void**)&w1lo, g_w1lo);
    cudaGetSymbolAddress((void**)&w3hi, g_w3hi); cudaGetSymbolAddress((void**)&w3lo, g_w3lo);
    cudaGetSymbolAddress((void**)&w2hi, g_w2hi); cudaGetSymbolAddress((void**)&w2lo, g_w2lo);

    cudaFuncSetAttribute(scores_mma_kernel,
                         cudaFuncAttributeMaxDynamicSharedMemorySize, SMS_TOTAL);
    cudaFuncSetAttribute(qproj_mma_kernel,
                         cudaFuncAttributeMaxDynamicSharedMemorySize, DO_TOTAL);
    cudaFuncSetAttribute(swiglu_mma_kernel,
                         cudaFuncAttributeMaxDynamicSharedMemorySize, DW_TOTAL);
    cudaFuncSetAttribute(out_mma_kernel,
                         cudaFuncAttributeMaxDynamicSharedMemorySize, DO_TOTAL);

    // launch 1: all pre-qproj prep fused
    prep_all_kernel<<<PREP_TOTAL_BLKS, 256>>>(keys, x, wq, bq, bn_gamma, bn_beta,
                                              bn_mean, bn_var);
    // launch 2
    qproj_mma_kernel<<<dim3(T_TOK / 128, QDIM / 64), 256, DO_TOTAL>>>();
    // launch 3 (independent filler so scores lands at launch 4 for ncu)
    split_kernel<<<(HID_S * D_DIM / 4 + 255) / 256, 256>>>(s_w1, w1hi, w1lo, HID_S * D_DIM / 4);
    // launch 4: the kernel we need profiled
    scores_mma_kernel<<<dim3(T_TOK / TOK_TILE, H_HEADS, KEY_SPLITS), 256, SMS_TOTAL>>>();
    // remaining
    split_kernel<<<(HID_S * D_DIM / 4 + 255) / 256, 256>>>(s_w3, w3hi, w3lo, HID_S * D_DIM / 4);
    split_kernel<<<(D_DIM * HID_S / 4 + 255) / 256, 256>>>(s_w2, w2hi, w2lo, D_DIM * HID_S / 4);
    rescore_kernel<<<T_TOK, 128>>>(keys);
    moe_small_kernel<<<T_TOK, 128>>>(x, w_down, w_up, a_w1, a_w2, a_w3);
    swiglu_mma_kernel<<<dim3(T_TOK / 128, HID_S / 64), 256, DW_TOTAL>>>();
    out_mma_kernel<<<dim3(T_TOK / 128, D_DIM / 64), 256, DO_TOTAL>>>(out);
}

// round 14
// speedup vs baseline: 1.2918x; 1.1999x over previous
#include <cuda_runtime.h>
#include <cuda_bf16.h>
#include <cfloat>
#include <math.h>
#include <cstdint>

#define T_TOK   2048
#define D_DIM   768
#define H_HEADS 4
#define N_KEYS  25600
#define KD      128
#define KNN     16
#define HID_A   44
#define HID_S   1024
#define QDIM    (H_HEADS*KD)   // 512
#define BN_EPS  1e-5f

#define KEY_SPLITS 4
#define KEYS_PER_SPLIT (N_KEYS / KEY_SPLITS)   // 6400
#define CHUNK_N 64
#define NCHUNK (KEYS_PER_SPLIT / CHUNK_N)      // 100
#define TOK_TILE 128
#define NCAND  (KEY_SPLITS * KNN)              // 64 candidates per (token, head)

// ---------------- scratch (device globals; no allocations allowed) ----------
__device__ __nv_bfloat16 g_qhi[T_TOK * QDIM];
__device__ float g_qf[T_TOK * QDIM];
__device__ __nv_bfloat16 g_khi[H_HEADS * N_KEYS * KD];
__device__ int   g_ptopi[T_TOK * H_HEADS * NCAND];
__device__ int   g_topidx[T_TOK * H_HEADS * KNN];
__device__ float g_gates[T_TOK * H_HEADS * KNN];
__device__ float g_comb[T_TOK];
__device__ float g_bnA[QDIM];
__device__ float g_bnB[QDIM];
// bf16 hi/lo operand splits
__device__ __nv_bfloat16 g_xhi[T_TOK * D_DIM];
__device__ __nv_bfloat16 g_xlo[T_TOK * D_DIM];
__device__ __nv_bfloat16 g_wqhi[QDIM * D_DIM];
__device__ __nv_bfloat16 g_wqlo[QDIM * D_DIM];
__device__ __nv_bfloat16 g_w1hi[HID_S * D_DIM];
__device__ __nv_bfloat16 g_w1lo[HID_S * D_DIM];
__device__ __nv_bfloat16 g_w3hi[HID_S * D_DIM];
__device__ __nv_bfloat16 g_w3lo[HID_S * D_DIM];
__device__ __nv_bfloat16 g_w2hi[D_DIM * HID_S];
__device__ __nv_bfloat16 g_w2lo[D_DIM * HID_S];
__device__ __nv_bfloat16 g_hidhi[T_TOK * HID_S];
__device__ __nv_bfloat16 g_hidlo[T_TOK * HID_S];

// ============================================================================
// helpers
// ============================================================================
__device__ __forceinline__ uint32_t smem_u32(const void* p) {
    uint32_t a;
    asm("{ .reg .u64 t; cvta.to.shared.u64 t, %1; cvt.u32.u64 %0, t; }" : "=r"(a) : "l"(p));
    return a;
}
#define CP_ASYNC16(dst, src) \
    asm volatile("cp.async.cg.shared.global [%0], [%1], 16;" :: "r"((uint32_t)(dst)), "l"(src))
#define CP_COMMIT() asm volatile("cp.async.commit_group;" ::: "memory")
#define CP_WAIT0()  asm volatile("cp.async.wait_group 0;" ::: "memory")

__device__ __forceinline__ void ldmx4(uint32_t& r0, uint32_t& r1, uint32_t& r2, uint32_t& r3,
                                      uint32_t addr) {
    asm volatile("ldmatrix.sync.aligned.m8n8.x4.shared.b16 {%0,%1,%2,%3}, [%4];"
                 : "=r"(r0), "=r"(r1), "=r"(r2), "=r"(r3) : "r"(addr));
}
__device__ __forceinline__ void mma_bf16(float* c, const uint32_t* a, const uint32_t* b) {
    asm volatile(
        "mma.sync.aligned.m16n8k16.row.col.f32.bf16.bf16.f32 "
        "{%0,%1,%2,%3}, {%4,%5,%6,%7}, {%8,%9}, {%0,%1,%2,%3};"
        : "+f"(c[0]), "+f"(c[1]), "+f"(c[2]), "+f"(c[3])
        : "r"(a[0]), "r"(a[1]), "r"(a[2]), "r"(a[3]), "r"(b[0]), "r"(b[1]));
}

// fully unrolled register insertion into sorted-desc list of 16 floats+ints
__device__ __forceinline__ void reg_insert16(float* tv, int* ti, float vv, int idx) {
#pragma unroll
    for (int p = KNN - 1; p > 0; --p) {
        bool shift = tv[p - 1] < vv;
        bool here  = !shift && (tv[p] < vv);
        float ntv = shift ? tv[p - 1] : (here ? vv : tv[p]);
        int   nti = shift ? ti[p - 1] : (here ? idx : ti[p]);
        tv[p] = ntv; ti[p] = nti;
    }
    if (tv[0] < vv) { tv[0] = vv; ti[0] = idx; }
}

// ---- packed-key top-16 machinery (scores kernel) ----
// key = (sortable_bf16(v) << 16) | key_index   (idx < 65536)
#define INIT_KEY 0x007F0000u   // packed -inf

__device__ __forceinline__ uint32_t pack_key(float v, int idx) {
    uint32_t b = (uint32_t)__bfloat16_as_ushort(__float2bfloat16(v));
    uint32_t m = (b & 0x8000u) ? 0xFFFFu : 0x8000u;
    return ((b ^ m) << 16) | (uint32_t)idx;
}
__device__ __forceinline__ float unpack_min(uint32_t key15) {
    uint32_t s = key15 >> 16;
    uint32_t m = (s & 0x8000u) ? 0x8000u : 0xFFFFu;
    return __uint_as_float((s ^ m) << 16);
}
// sorted-desc insert on packed keys: 2 setp + 2 sel per slot
__device__ __forceinline__ void ins16u(uint32_t* L, uint32_t key) {
#pragma unroll
    for (int p = KNN - 1; p > 0; --p) {
        uint32_t up = L[p - 1];
        L[p] = (up < key) ? up : ((L[p] < key) ? key : L[p]);
    }
    if (L[0] < key) L[0] = key;
}

// ============================================================================
// prep_all: keysprep + split(x) + split(wq) + bnprep in one launch
// ============================================================================
#define PREP_KEY_BLKS ((H_HEADS * N_KEYS * KD) / (256 * 4))
#define PREP_X_BLKS   ((T_TOK * D_DIM) / (256 * 4))
#define PREP_WQ_BLKS  ((QDIM * D_DIM) / (256 * 4))
#define PREP_BN_BLKS  ((QDIM + 255) / 256)
#define PREP_TOTAL_BLKS (PREP_KEY_BLKS + PREP_X_BLKS + PREP_WQ_BLKS + PREP_BN_BLKS)

__global__ void prep_all_kernel(const float* __restrict__ keys,
                                const float* __restrict__ x,
                                const float* __restrict__ wq,
                                const float* __restrict__ bq,
                                const float* __restrict__ gamma,
                                const float* __restrict__ beta,
                                const float* __restrict__ mean,
                                const float* __restrict__ var)
{
    int b = blockIdx.x;
    if (b < PREP_KEY_BLKS) {
        size_t i = (size_t)b * 256 + threadIdx.x;
        const float4 v = ((const float4*)keys)[i];
        ((__nv_bfloat162*)g_khi)[2 * i] =
            __nv_bfloat162(__float2bfloat16(v.x), __float2bfloat16(v.y));
        ((__nv_bfloat162*)g_khi)[2 * i + 1] =
            __nv_bfloat162(__float2bfloat16(v.z), __float2bfloat16(v.w));
        return;
    }
    b -= PREP_KEY_BLKS;
    if (b < PREP_X_BLKS + PREP_WQ_BLKS) {
        const float* src;
        __nv_bfloat16 *hi, *lo;
        size_t i;
        if (b < PREP_X_BLKS) {
            src = x; hi = g_xhi; lo = g_xlo;
            i = (size_t)b * 256 + threadIdx.x;
        } else {
            src = wq; hi = g_wqhi; lo = g_wqlo;
            i = (size_t)(b - PREP_X_BLKS) * 256 + threadIdx.x;
        }
        float4 v = ((const float4*)src)[i];
        float f[4] = {v.x, v.y, v.z, v.w};
        __nv_bfloat16 h[4], l[4];
#pragma unroll
        for (int k = 0; k < 4; ++k) {
            h[k] = __float2bfloat16(f[k]);
            l[k] = __float2bfloat16(f[k] - __bfloat162float(h[k]));
        }
        ((__nv_bfloat162*)hi)[2 * i]     = __nv_bfloat162(h[0], h[1]);
        ((__nv_bfloat162*)hi)[2 * i + 1] = __nv_bfloat162(h[2], h[3]);
        ((__nv_bfloat162*)lo)[2 * i]     = __nv_bfloat162(l[0], l[1]);
        ((__nv_bfloat162*)lo)[2 * i + 1] = __nv_bfloat162(l[2], l[3]);
        return;
    }
    b -= PREP_X_BLKS + PREP_WQ_BLKS;
    {
        int n = b * 256 + threadIdx.x;
        if (n < QDIM) {
            float sc = gamma[n] * rsqrtf(var[n] + BN_EPS);
            g_bnA[n] = sc;
            g_bnB[n] = (bq[n] - mean[n]) * sc + beta[n];
        }
    }
}

// ============================================================================
// split: fp32 -> bf16 hi + lo residual
// ============================================================================
__global__ void split_kernel(const float* __restrict__ src,
                             __nv_bfloat16* __restrict__ hi,
                             __nv_bfloat16* __restrict__ lo, int n4)
{
    int i = blockIdx.x * 256 + threadIdx.x;
    if (i >= n4) return;
    float4 v = ((const float4*)src)[i];
    float f[4] = {v.x, v.y, v.z, v.w};
    __nv_bfloat16 h[4], l[4];
#pragma unroll
    for (int k = 0; k < 4; ++k) {
        h[k] = __float2bfloat16(f[k]);
        l[k] = __float2bfloat16(f[k] - __bfloat162float(h[k]));
    }
    ((__nv_bfloat162*)hi)[2 * i]     = __nv_bfloat162(h[0], h[1]);
    ((__nv_bfloat162*)hi)[2 * i + 1] = __nv_bfloat162(h[2], h[3]);
    ((__nv_bfloat162*)lo)[2 * i]     = __nv_bfloat162(l[0], l[1]);
    ((__nv_bfloat162*)lo)[2 * i + 1] = __nv_bfloat162(l[2], l[3]);
}

// ============================================================================
#define AB_STRIDE 272

// ============================================================================
// Kernel 1: qproj via HMMA 4-term split (unchanged)
// ============================================================================
#define DO_AH 0
#define DO_AL 34816
#define DO_BH 69632
#define DO_BL (69632 + 17408)
#define DO_TOTAL (69632 + 2*17408)   // 104448

__global__ void __launch_bounds__(256, 2) qproj_mma_kernel()
{
    extern __shared__ char smem[];
    const uint32_t smb = smem_u32(smem);
    const int tid  = threadIdx.x;
    const int wid  = tid >> 5;
    const int lane = tid & 31;
    const int m0 = blockIdx.x * 128;
    const int n0 = blockIdx.y * 64;

    const int warp_m = wid >> 1;
    const int warp_n = wid & 1;

    const uint32_t a_row_off = (uint32_t)((warp_m * 32 + (lane & 15)) * AB_STRIDE + (lane >> 4) * 16);
    const uint32_t b_row_off = (uint32_t)((warp_n * 32 + (lane & 7) + ((lane >> 4) << 3)) * AB_STRIDE
                                          + ((lane >> 3) & 1) * 16);

    float C[2][4][4] = {};

    const char* axh = (const char*)(g_xhi + (size_t)m0 * D_DIM);
    const char* axl = (const char*)(g_xlo + (size_t)m0 * D_DIM);
    const char* bh_ = (const char*)(g_wqhi + (size_t)n0 * D_DIM);
    const char* bl_ = (const char*)(g_wqlo + (size_t)n0 * D_DIM);

    for (int kc = 0; kc < D_DIM / 128; ++kc) {
        if (kc) __syncthreads();
        const uint32_t ko = (uint32_t)(kc * 256);
#pragma unroll
        for (int it = 0; it < 8; ++it) {
            int idx = tid + it * 256;
            int r = idx >> 4, seg = idx & 15;
            uint32_t d = (uint32_t)(r * AB_STRIDE + seg * 16);
            uint32_t s = (uint32_t)(r * (D_DIM * 2)) + ko + seg * 16;
            CP_ASYNC16(smb + DO_AH + d, axh + s);
            CP_ASYNC16(smb + DO_AL + d, axl + s);
        }
#pragma unroll
        for (int it = 0; it < 4; ++it) {
            int idx = tid + it * 256;
            int r = idx >> 4, seg = idx & 15;
            uint32_t d = (uint32_t)(r * AB_STRIDE + seg * 16);
            uint32_t s = (uint32_t)(r * (D_DIM * 2)) + ko + seg * 16;
            CP_ASYNC16(smb + DO_BH + d, bh_ + s);
            CP_ASYNC16(smb + DO_BL + d, bl_ + s);
        }
        CP_COMMIT(); CP_WAIT0();
        __syncthreads();

#pragma unroll
        for (int ks = 0; ks < 8; ++ks) {
            const uint32_t koff = (uint32_t)(ks * 32);
            uint32_t bH[8], bL[8];
            ldmx4(bH[0], bH[1], bH[2], bH[3], smb + DO_BH + b_row_off + koff);
            ldmx4(bH[4], bH[5], bH[6], bH[7], smb + DO_BH + b_row_off + koff + 16 * AB_STRIDE);
            ldmx4(bL[0], bL[1], bL[2], bL[3], smb + DO_BL + b_row_off + koff);
            ldmx4(bL[4], bL[5], bL[6], bL[7], smb + DO_BL + b_row_off + koff + 16 * AB_STRIDE);
#pragma unroll
            for (int i = 0; i < 2; ++i) {
                uint32_t ah[4], al[4];
                ldmx4(ah[0], ah[1], ah[2], ah[3],
                      smb + DO_AH + a_row_off + koff + (uint32_t)(i * 16 * AB_STRIDE));
                ldmx4(al[0], al[1], al[2], al[3],
                      smb + DO_AL + a_row_off + koff + (uint32_t)(i * 16 * AB_STRIDE));
#pragma unroll
                for (int j = 0; j < 4; ++j) {
                    mma_bf16(C[i][j], ah, bH + 2 * j);
                    mma_bf16(C[i][j], ah, bL + 2 * j);
                    mma_bf16(C[i][j], al, bH + 2 * j);
                    mma_bf16(C[i][j], al, bL + 2 * j);
                }
            }
        }
    }

    const int trow = lane >> 2;
    const int tcol = (lane & 3) * 2;
#pragma unroll
    for (int i = 0; i < 2; ++i) {
#pragma unroll
        for (int half = 0; half < 2; ++half) {
            int m = m0 + warp_m * 32 + i * 16 + trow + half * 8;
#pragma unroll
            for (int j = 0; j < 4; ++j) {
                int n = n0 + warp_n * 32 + j * 8 + tcol;
                float va = C[i][j][2 * half]     * g_bnA[n]     + g_bnB[n];
                float vb = C[i][j][2 * half + 1] * g_bnA[n + 1] + g_bnB[n + 1];
                *(float2*)(g_qf + (size_t)m * QDIM + n) = make_float2(va, vb);
                *(__nv_bfloat162*)(g_qhi + (size_t)m * QDIM + n) =
                    __nv_bfloat162(__float2bfloat16(va), __float2bfloat16(vb));
            }
        }
    }
}

// ============================================================================
// Kernel 2: pass-1 scores — register scan with PACKED-KEY top-16 lists and
// fmax-pair prescreen. 256 threads, 8 warps x (16 tok x 64 keys). 2 CTAs/SM.
// ============================================================================
#define SMS_A     0            // 128*272 = 34816
#define SMS_B0    34816        // 64*272 = 17408
#define SMS_B1    52224
#define SMS_TOTAL 69632

__global__ void __launch_bounds__(256, 2) scores_mma_kernel()
{
    extern __shared__ char smem[];
    const uint32_t smb = smem_u32(smem);
    const int tid  = threadIdx.x;
    const int wid  = tid >> 5;       // 0..7 -> tokens 16*wid
    const int lane = tid & 31;

    const int t0 = blockIdx.x * TOK_TILE;
    const int h  = blockIdx.y;
    const int z  = blockIdx.z;
    const int keybase = z * KEYS_PER_SPLIT;

    uint32_t bdst[4], bsrc[4];
#pragma unroll
    for (int i = 0; i < 4; ++i) {
        int idx = tid + i * 256;
        int r = idx >> 4, seg = idx & 15;
        bdst[i] = (uint32_t)(r * AB_STRIDE + seg * 16);
        bsrc[i] = (uint32_t)(r * 256 + seg * 16);
    }

    {
        const char* qh = (const char*)(g_qhi + (size_t)t0 * QDIM + h * KD);
#pragma unroll
        for (int i = 0; i < 8; ++i) {
            int idx = tid + i * 256;
            int r = idx >> 4, seg = idx & 15;
            CP_ASYNC16(smb + SMS_A + (uint32_t)(r * AB_STRIDE + seg * 16),
                       qh + (size_t)r * (QDIM * 2) + seg * 16);
        }
    }
    const char* khbase = (const char*)(g_khi + ((size_t)h * N_KEYS + keybase) * KD);
    {
#pragma unroll
        for (int i = 0; i < 4; ++i) CP_ASYNC16(smb + SMS_B0 + bdst[i], khbase + bsrc[i]);
        CP_COMMIT();
    }

    // packed top-16 lists: streams A (row trow) and B (row trow+8)
    uint32_t LA[KNN], LB[KNN];
#pragma unroll
    for (int k = 0; k < KNN; ++k) { LA[k] = INIT_KEY; LB[k] = INIT_KEY; }
    float minvA = -FLT_MAX, minvB = -FLT_MAX;

    const uint32_t a_row_off = (uint32_t)((wid * 16 + (lane & 15)) * AB_STRIDE + (lane >> 4) * 16);
    const uint32_t b_row_off = (uint32_t)(((lane & 7) + ((lane >> 4) << 3)) * AB_STRIDE
                                          + ((lane >> 3) & 1) * 16);

    const int tcol = (lane & 3) * 2;

    for (int c = 0; c < NCHUNK; ++c) {
        const uint32_t bbase = (c & 1) ? (smb + SMS_B1) : (smb + SMS_B0);
        CP_WAIT0();
        __syncthreads();

        if (c + 1 < NCHUNK) {
            const uint32_t obase = (c & 1) ? (smb + SMS_B0) : (smb + SMS_B1);
            const uint32_t cb = (uint32_t)((c + 1) * CHUNK_N * KD * 2);
#pragma unroll
            for (int i = 0; i < 4; ++i) CP_ASYNC16(obase + bdst[i], khbase + cb + bsrc[i]);
            CP_COMMIT();
        }

        float C[8][4];
#pragma unroll
        for (int j = 0; j < 8; ++j)
#pragma unroll
            for (int e = 0; e < 4; ++e) C[j][e] = 0.f;

#pragma unroll
        for (int ks = 0; ks < 8; ++ks) {
            const uint32_t koff = (uint32_t)(ks * 32);
            uint32_t bh[16], ah[4];
            ldmx4(bh[0],  bh[1],  bh[2],  bh[3],  bbase + b_row_off + koff);
            ldmx4(bh[4],  bh[5],  bh[6],  bh[7],  bbase + b_row_off + koff + 16 * AB_STRIDE);
            ldmx4(bh[8],  bh[9],  bh[10], bh[11], bbase + b_row_off + koff + 32 * AB_STRIDE);
            ldmx4(bh[12], bh[13], bh[14], bh[15], bbase + b_row_off + koff + 48 * AB_STRIDE);
            ldmx4(ah[0], ah[1], ah[2], ah[3], smb + SMS_A + a_row_off + koff);
#pragma unroll
            for (int j = 0; j < 8; ++j) mma_bf16(C[j], ah, bh + 2 * j);
        }

        // register-resident scan with fmax-pair prescreen + packed inserts
        const int kb = keybase + c * CHUNK_N + tcol;
#pragma unroll
        for (int j = 0; j < 8; ++j) {
            const int i0 = kb + j * 8, i1 = i0 + 1;
            float v0 = C[j][0], v1 = C[j][1];
            if (fmaxf(v0, v1) > minvA) {
                if (v0 > minvA) { ins16u(LA, pack_key(v0, i0)); minvA = unpack_min(LA[KNN - 1]); }
                if (v1 > minvA) { ins16u(LA, pack_key(v1, i1)); minvA = unpack_min(LA[KNN - 1]); }
            }
            float v2 = C[j][2], v3 = C[j][3];
            if (fmaxf(v2, v3) > minvB) {
                if (v2 > minvB) { ins16u(LB, pack_key(v2, i0)); minvB = unpack_min(LB[KNN - 1]); }
                if (v3 > minvB) { ins16u(LB, pack_key(v3, i1)); minvB = unpack_min(LB[KNN - 1]); }
            }
        }
    }

    // merge the 4 lanes of each trow group (lanes 4t..4t+3) via shfl
    {
        uint32_t ov[KNN];
        // ---- list A ----
#pragma unroll
        for (int k = 0; k < KNN; ++k) ov[k] = __shfl_down_sync(0xffffffffu, LA[k], 1);
        if ((lane & 1) == 0) {
#pragma unroll
            for (int k = 0; k < KNN; ++k)
                if (ov[k] > LA[KNN - 1]) ins16u(LA, ov[k]);
        }
#pragma unroll
        for (int k = 0; k < KNN; ++k) ov[k] = __shfl_down_sync(0xffffffffu, LA[k], 2);
        if ((lane & 3) == 0) {
#pragma unroll
            for (int k = 0; k < KNN; ++k)
                if (ov[k] > LA[KNN - 1]) ins16u(LA, ov[k]);
        }
        // ---- list B ----
#pragma unroll
        for (int k = 0; k < KNN; ++k) ov[k] = __shfl_down_sync(0xffffffffu, LB[k], 1);
        if ((lane & 1) == 0) {
#pragma unroll
            for (int k = 0; k < KNN; ++k)
                if (ov[k] > LB[KNN - 1]) ins16u(LB, ov[k]);
        }
#pragma unroll
        for (int k = 0; k < KNN; ++k) ov[k] = __shfl_down_sync(0xffffffffu, LB[k], 2);
        if ((lane & 3) == 0) {
#pragma unroll
            for (int k = 0; k < KNN; ++k)
                if (ov[k] > LB[KNN - 1]) ins16u(LB, ov[k]);
            int tA = t0 + wid * 16 + (lane >> 2);
            int tB = tA + 8;
            size_t pbA = (((size_t)tA * H_HEADS + h) * KEY_SPLITS + z) * KNN;
            size_t pbB = (((size_t)tB * H_HEADS + h) * KEY_SPLITS + z) * KNN;
#pragma unroll
            for (int k = 0; k < KNN; ++k) {
                g_ptopi[pbA + k] = (int)(LA[k] & 0xFFFFu);
                g_ptopi[pbB + k] = (int)(LB[k] & 0xFFFFu);
            }
        }
    }
}

// ============================================================================
// Kernel 2b: exact fp32 rescore of 64 candidates (unchanged)
// ============================================================================
__global__ void __launch_bounds__(128) rescore_kernel(const float* __restrict__ keys)
{
    const int t = blockIdx.x;
    const int h = threadIdx.x >> 5;
    const int lane = threadIdx.x & 31;
    const int bh = t * H_HEADS + h;

    __shared__ float sq[H_HEADS][KD];
    *(float4*)(&sq[h][lane * 4]) = *(const float4*)(g_qf + (size_t)t * QDIM + h * KD + lane * 4);
    __syncwarp();

    const int idx0 = g_ptopi[(size_t)bh * NCAND + lane];
    const int idx1 = g_ptopi[(size_t)bh * NCAND + 32 + lane];
    const float4* kr0 = (const float4*)(keys + ((size_t)h * N_KEYS + idx0) * KD);
    const float4* kr1 = (const float4*)(keys + ((size_t)h * N_KEYS + idx1) * KD);
    float acc0 = 0.f, acc1 = 0.f;
#pragma unroll
    for (int d4 = 0; d4 < KD / 4; ++d4) {
        float4 k0 = kr0[d4], k1 = kr1[d4];
        float q0 = sq[h][4 * d4 + 0], q1 = sq[h][4 * d4 + 1];
        float q2 = sq[h][4 * d4 + 2], q3 = sq[h][4 * d4 + 3];
        acc0 = fmaf(k0.x, q0, acc0); acc0 = fmaf(k0.y, q1, acc0);
        acc0 = fmaf(k0.z, q2, acc0); acc0 = fmaf(k0.w, q3, acc0);
        acc1 = fmaf(k1.x, q0, acc1); acc1 = fmaf(k1.y, q1, acc1);
        acc1 = fmaf(k1.z, q2, acc1); acc1 = fmaf(k1.w, q3, acc1);
    }

    int rank0 = 0, rank1 = 0;
#pragma unroll
    for (int j = 0; j < 32; ++j) {
        float v0 = __shfl_sync(0xffffffffu, acc0, j);
        float v1 = __shfl_sync(0xffffffffu, acc1, j);
        rank0 += (v0 > acc0) || (v0 == acc0 && j < lane);
        rank0 += (v1 > acc0);
        rank1 += (v0 > acc1) || (v0 == acc1);
        rank1 += (v1 > acc1) || (v1 == acc1 && j < lane);
    }

    float vmax = fmaxf(acc0, acc1);
#pragma unroll
    for (int off = 16; off > 0; off >>= 1)
        vmax = fmaxf(vmax, __shfl_xor_sync(0xffffffffu, vmax, off));
    float e0 = (rank0 < KNN) ? __expf(acc0 - vmax) : 0.f;
    float e1 = (rank1 < KNN) ? __expf(acc1 - vmax) : 0.f;
    float sum = e0 + e1;
#pragma unroll
    for (int off = 16; off > 0; off >>= 1)
        sum += __shfl_xor_sync(0xffffffffu, sum, off);
    float inv = 1.f / sum;
    if (rank0 < KNN) {
        g_gates[(size_t)bh * KNN + rank0]  = e0 * inv;
        g_topidx[(size_t)bh * KNN + rank0] = idx0;
    }
    if (rank1 < KNN) {
        g_gates[(size_t)bh * KNN + rank1]  = e1 * inv;
        g_topidx[(size_t)bh * KNN + rank1] = idx1;
    }
}

// ============================================================================
// Kernel 3: tiny PEER expert network per token (unchanged)
// ============================================================================
__global__ void moe_small_kernel(const float* __restrict__ x,
                                 const float* __restrict__ wdown,
                                 const float* __restrict__ wup,
                                 const float* __restrict__ aw1,
                                 const float* __restrict__ aw2,
                                 const float* __restrict__ aw3)
{
    __shared__ float s_aw1[HID_A * KNN];
    __shared__ float s_aw3[HID_A * KNN];
    __shared__ float s_aw2[KNN * HID_A];
    __shared__ float s_z[H_HEADS][KNN];
    __shared__ float s_hid[H_HEADS][HID_A];
    __shared__ float s_red[H_HEADS];
    __shared__ float s_wred[4];
    __shared__ float s_xsum;

    const int t = blockIdx.x;
    const int tid = threadIdx.x;
    const int w = tid >> 5;
    const int lane = tid & 31;

    for (int i = tid; i < HID_A * KNN; i += 128) { s_aw1[i] = aw1[i]; s_aw3[i] = aw3[i]; s_aw2[i] = aw2[i]; }

    float ps = 0.f;
    for (int i = tid; i < D_DIM; i += 128) ps += x[(size_t)t * D_DIM + i];
#pragma unroll
    for (int off = 16; off > 0; off >>= 1) ps += __shfl_down_sync(0xffffffffu, ps, off);
    if (lane == 0) s_wred[w] = ps;
    __syncthreads();
    if (tid == 0) s_xsum = s_wred[0] + s_wred[1] + s_wred[2] + s_wred[3];
    __syncthreads();
    const float xsum = s_xsum;

    const size_t gbase = ((size_t)t * H_HEADS + w) * KNN;
    if (lane < KNN)
        s_z[w][lane] = xsum * wdown[g_topidx[gbase + lane]];
    __syncwarp();

    for (int a = lane; a < HID_A; a += 32) {
        float d1 = 0.f, d3 = 0.f;
#pragma unroll
        for (int k = 0; k < KNN; ++k) {
            float zz = s_z[w][k];
            d1 = fmaf(zz, s_aw1[a * KNN + k], d1);
            d3 = fmaf(zz, s_aw3[a * KNN + k], d3);
        }
        float sl = d1 / (1.f + __expf(-d1));
        s_hid[w][a] = sl * d3;
    }
    __syncwarp();

    float part = 0.f;
    if (lane < KNN) {
        float o = 0.f;
#pragma unroll
        for (int a = 0; a < HID_A; ++a) o = fmaf(s_hid[w][a], s_aw2[lane * HID_A + a], o);
        int id = g_topidx[gbase + lane];
        part = o * g_gates[gbase + lane] * wup[id];
    }
#pragma unroll
    for (int off = 16; off > 0; off >>= 1) part += __shfl_down_sync(0xffffffffu, part, off);
    if (lane == 0) s_red[w] = part;
    __syncthreads();
    if (tid == 0) g_comb[t] = s_red[0] + s_red[1] + s_red[2] + s_red[3];
}

// ============================================================================
// Kernel 4: swiglu via HMMA 3-term split (unchanged)
// ============================================================================
#define DW_AH 0
#define DW_AL 34816
#define DW_B  69632
#define DW_BSZ 17408
#define DW_TOTAL (DW_B + 4*DW_BSZ)

__global__ void __launch_bounds__(256, 1) swiglu_mma_kernel()
{
    extern __shared__ char smem[];
    const uint32_t smb = smem_u32(smem);
    const int tid  = threadIdx.x;
    const int wid  = tid >> 5;
    const int lane = tid & 31;
    const int m0 = blockIdx.x * 128;
    const int n0 = blockIdx.y * 64;

    const int warp_m = wid >> 1;
    const int warp_n = wid & 1;

    const uint32_t a_row_off = (uint32_t)((warp_m * 32 + (lane & 15)) * AB_STRIDE + (lane >> 4) * 16);
    const uint32_t b_row_off = (uint32_t)((warp_n * 32 + (lane & 7) + ((lane >> 4) << 3)) * AB_STRIDE
                                          + ((lane >> 3) & 1) * 16);

    float C1[2][4][4] = {};
    float C3[2][4][4] = {};

    const char* axh = (const char*)(g_xhi + (size_t)m0 * D_DIM);
    const char* axl = (const char*)(g_xlo + (size_t)m0 * D_DIM);
    const char* b1h = (const char*)(g_w1hi + (size_t)n0 * D_DIM);
    const char* b1l = (const char*)(g_w1lo + (size_t)n0 * D_DIM);
    const char* b3h = (const char*)(g_w3hi + (size_t)n0 * D_DIM);
    const char* b3l = (const char*)(g_w3lo + (size_t)n0 * D_DIM);

    for (int kc = 0; kc < D_DIM / 128; ++kc) {
        if (kc) __syncthreads();
        const uint32_t ko = (uint32_t)(kc * 256);
#pragma unroll
        for (int it = 0; it < 8; ++it) {
            int idx = tid + it * 256;
            int r = idx >> 4, seg = idx & 15;
            uint32_t d = (uint32_t)(r * AB_STRIDE + seg * 16);
            uint32_t s = (uint32_t)(r * (D_DIM * 2)) + ko + seg * 16;
            CP_ASYNC16(smb + DW_AH + d, axh + s);
            CP_ASYNC16(smb + DW_AL + d, axl + s);
        }
#pragma unroll
        for (int it = 0; it < 4; ++it) {
            int idx = tid + it * 256;
            int r = idx >> 4, seg = idx & 15;
            uint32_t d = (uint32_t)(r * AB_STRIDE + seg * 16);
            uint32_t s = (uint32_t)(r * (D_DIM * 2)) + ko + seg * 16;
            CP_ASYNC16(smb + DW_B + 0 * DW_BSZ + d, b1h + s);
            CP_ASYNC16(smb + DW_B + 1 * DW_BSZ + d, b1l + s);
            CP_ASYNC16(smb + DW_B + 2 * DW_BSZ + d, b3h + s);
            CP_ASYNC16(smb + DW_B + 3 * DW_BSZ + d, b3l + s);
        }
        CP_COMMIT(); CP_WAIT0();
        __syncthreads();

#pragma unroll
        for (int ks = 0; ks < 8; ++ks) {
            const uint32_t koff = (uint32_t)(ks * 32);
            uint32_t b1H[8], b1L[8], b3H[8], b3L[8];
            ldmx4(b1H[0], b1H[1], b1H[2], b1H[3], smb + DW_B + 0 * DW_BSZ + b_row_off + koff);
            ldmx4(b1H[4], b1H[5], b1H[6], b1H[7], smb + DW_B + 0 * DW_BSZ + b_row_off + koff + 16 * AB_STRIDE);
            ldmx4(b1L[0], b1L[1], b1L[2], b1L[3], smb + DW_B + 1 * DW_BSZ + b_row_off + koff);
            ldmx4(b1L[4], b1L[5], b1L[6], b1L[7], smb + DW_B + 1 * DW_BSZ + b_row_off + koff + 16 * AB_STRIDE);
            ldmx4(b3H[0], b3H[1], b3H[2], b3H[3], smb + DW_B + 2 * DW_BSZ + b_row_off + koff);
            ldmx4(b3H[4], b3H[5], b3H[6], b3H[7], smb + DW_B + 2 * DW_BSZ + b_row_off + koff + 16 * AB_STRIDE);
            ldmx4(b3L[0], b3L[1], b3L[2], b3L[3], smb + DW_B + 3 * DW_BSZ + b_row_off + koff);
            ldmx4(b3L[4], b3L[5], b3L[6], b3L[7], smb + DW_B + 3 * DW_BSZ + b_row_off + koff + 16 * AB_STRIDE);
#pragma unroll
            for (int i = 0; i < 2; ++i) {
                uint32_t ah[4], al[4];
                ldmx4(ah[0], ah[1], ah[2], ah[3],
                      smb + DW_AH + a_row_off + koff + (uint32_t)(i * 16 * AB_STRIDE));
                ldmx4(al[0], al[1], al[2], al[3],
                      smb + DW_AL + a_row_off + koff + (uint32_t)(i * 16 * AB_STRIDE));
#pragma unroll
                for (int j = 0; j < 4; ++j) {
                    mma_bf16(C1[i][j], ah, b1H + 2 * j);
                    mma_bf16(C1[i][j], ah, b1L + 2 * j);
                    mma_bf16(C1[i][j], al, b1H + 2 * j);
                    mma_bf16(C3[i][j], ah, b3H + 2 * j);
                    mma_bf16(C3[i][j], ah, b3L + 2 * j);
                    mma_bf16(C3[i][j], al, b3H + 2 * j);
                }
            }
        }
    }

    const int trow = lane >> 2;
    const int tcol = (lane & 3) * 2;
#pragma unroll
    for (int i = 0; i < 2; ++i) {
#pragma unroll
        for (int j = 0; j < 4; ++j) {
            int n = n0 + warp_n * 32 + j * 8 + tcol;
#pragma unroll
            for (int half = 0; half < 2; ++half) {
                int m = m0 + warp_m * 32 + i * 16 + trow + half * 8;
                float z1a = C1[i][j][2 * half], z1b = C1[i][j][2 * half + 1];
                float z3a = C3[i][j][2 * half], z3b = C3[i][j][2 * half + 1];
                float va = (z1a / (1.f + __expf(-z1a))) * z3a;
                float vb = (z1b / (1.f + __expf(-z1b))) * z3b;
                __nv_bfloat16 ha = __float2bfloat16(va);
                __nv_bfloat16 hb = __float2bfloat16(vb);
                __nv_bfloat16 la = __float2bfloat16(va - __bfloat162float(ha));
                __nv_bfloat16 lb = __float2bfloat16(vb - __bfloat162float(hb));
                *(__nv_bfloat162*)(g_hidhi + (size_t)m * HID_S + n) = __nv_bfloat162(ha, hb);
                *(__nv_bfloat162*)(g_hidlo + (size_t)m * HID_S + n) = __nv_bfloat162(la, lb);
            }
        }
    }
}

// ============================================================================
// Kernel 5: out = hid @ w2^T + comb (unchanged)
// ============================================================================
__global__ void __launch_bounds__(256, 1) out_mma_kernel(float* __restrict__ out)
{
    extern __shared__ char smem[];
    const uint32_t smb = smem_u32(smem);
    const int tid  = threadIdx.x;
    const int wid  = tid >> 5;
    const int lane = tid & 31;
    const int m0 = blockIdx.x * 128;
    const int n0 = blockIdx.y * 64;

    const int warp_m = wid >> 1;
    const int warp_n = wid & 1;

    const uint32_t a_row_off = (uint32_t)((warp_m * 32 + (lane & 15)) * AB_STRIDE + (lane >> 4) * 16);
    const uint32_t b_row_off = (uint32_t)((warp_n * 32 + (lane & 7) + ((lane >> 4) << 3)) * AB_STRIDE
                                          + ((lane >> 3) & 1) * 16);

    float C[2][4][4] = {};

    const char* axh = (const char*)(g_hidhi + (size_t)m0 * HID_S);
    const char* axl = (const char*)(g_hidlo + (size_t)m0 * HID_S);
    const char* bh_ = (const char*)(g_w2hi + (size_t)n0 * HID_S);
    const char* bl_ = (const char*)(g_w2lo + (size_t)n0 * HID_S);

    for (int kc = 0; kc < HID_S / 128; ++kc) {
        if (kc) __syncthreads();
        const uint32_t ko = (uint32_t)(kc * 256);
#pragma unroll
        for (int it = 0; it < 8; ++it) {
            int idx = tid + it * 256;
            int r = idx >> 4, seg = idx & 15;
            uint32_t d = (uint32_t)(r * AB_STRIDE + seg * 16);
            uint32_t s = (uint32_t)(r * (HID_S * 2)) + ko + seg * 16;
            CP_ASYNC16(smb + DO_AH + d, axh + s);
            CP_ASYNC16(smb + DO_AL + d, axl + s);
        }
#pragma unroll
        for (int it = 0; it < 4; ++it) {
            int idx = tid + it * 256;
            int r = idx >> 4, seg = idx & 15;
            uint32_t d = (uint32_t)(r * AB_STRIDE + seg * 16);
            uint32_t s = (uint32_t)(r * (HID_S * 2)) + ko + seg * 16;
            CP_ASYNC16(smb + DO_BH + d, bh_ + s);
            CP_ASYNC16(smb + DO_BL + d, bl_ + s);
        }
        CP_COMMIT(); CP_WAIT0();
        __syncthreads();

#pragma unroll
        for (int ks = 0; ks < 8; ++ks) {
            const uint32_t koff = (uint32_t)(ks * 32);
            uint32_t bH[8], bL[8];
            ldmx4(bH[0], bH[1], bH[2], bH[3], smb + DO_BH + b_row_off + koff);
            ldmx4(bH[4], bH[5], bH[6], bH[7], smb + DO_BH + b_row_off + koff + 16 * AB_STRIDE);
            ldmx4(bL[0], bL[1], bL[2], bL[3], smb + DO_BL + b_row_off + koff);
            ldmx4(bL[4], bL[5], bL[6], bL[7], smb + DO_BL + b_row_off + koff + 16 * AB_STRIDE);
#pragma unroll
            for (int i = 0; i < 2; ++i) {
                uint32_t ah[4], al[4];
                ldmx4(ah[0], ah[1], ah[2], ah[3],
                      smb + DO_AH + a_row_off + koff + (uint32_t)(i * 16 * AB_STRIDE));
                ldmx4(al[0], al[1], al[2], al[3],
                      smb + DO_AL + a_row_off + koff + (uint32_t)(i * 16 * AB_STRIDE));
#pragma unroll
                for (int j = 0; j < 4; ++j) {
                    mma_bf16(C[i][j], ah, bH + 2 * j);
                    mma_bf16(C[i][j], ah, bL + 2 * j);
                    mma_bf16(C[i][j], al, bH + 2 * j);
                }
            }
        }
    }

    const int trow = lane >> 2;
    const int tcol = (lane & 3) * 2;
#pragma unroll
    for (int i = 0; i < 2; ++i) {
#pragma unroll
        for (int half = 0; half < 2; ++half) {
            int m = m0 + warp_m * 32 + i * 16 + trow + half * 8;
            float cb = g_comb[m];
#pragma unroll
            for (int j = 0; j < 4; ++j) {
                int n = n0 + warp_n * 32 + j * 8 + tcol;
                *(float2*)(out + (size_t)m * D_DIM + n) =
                    make_float2(C[i][j][2 * half] + cb, C[i][j][2 * half + 1] + cb);
            }
        }
    }
}

// ============================================================================
extern "C" void kernel_launch(void* const* d_in, const int* in_sizes, int n_in,
                              void* d_out, int out_size)
{
    const float* x        = (const float*)d_in[0];
    const float* wq       = (const float*)d_in[1];
    const float* bq       = (const float*)d_in[2];
    const float* bn_gamma = (const float*)d_in[3];
    const float* bn_beta  = (const float*)d_in[4];
    const float* bn_mean  = (const float*)d_in[5];
    const float* bn_var   = (const float*)d_in[6];
    const float* keys     = (const float*)d_in[7];
    const float* w_down   = (const float*)d_in[8];
    const float* w_up     = (const float*)d_in[9];
    const float* a_w1     = (const float*)d_in[10];
    const float* a_w2     = (const float*)d_in[11];
    const float* a_w3     = (const float*)d_in[12];
    const float* s_w1     = (const float*)d_in[13];
    const float* s_w2     = (const float*)d_in[14];
    const float* s_w3     = (const float*)d_in[15];
    float* out            = (float*)d_out;

    __nv_bfloat16 *w1hi, *w1lo, *w3hi, *w3lo, *w2hi, *w2lo;
    cudaGetSymbolAddress((void**)&w1hi, g_w1hi); cudaGetSymbolAddress((void**)&w1lo, g_w1lo);
    cudaGetSymbolAddress((void**)&w3hi, g_w3hi); cudaGetSymbolAddress((void**)&w3lo, g_w3lo);
    cudaGetSymbolAddress((void**)&w2hi, g_w2hi); cudaGetSymbolAddress((void**)&w2lo, g_w2lo);

    cudaFuncSetAttribute(scores_mma_kernel,
                         cudaFuncAttributeMaxDynamicSharedMemorySize, SMS_TOTAL);
    cudaFuncSetAttribute(qproj_mma_kernel,
                         cudaFuncAttributeMaxDynamicSharedMemorySize, DO_TOTAL);
    cudaFuncSetAttribute(swiglu_mma_kernel,
                         cudaFuncAttributeMaxDynamicSharedMemorySize, DW_TOTAL);
    cudaFuncSetAttribute(out_mma_kernel,
                         cudaFuncAttributeMaxDynamicSharedMemorySize, DO_TOTAL);

    // launch 1: all pre-qproj prep fused
    prep_all_kernel<<<PREP_TOTAL_BLKS, 256>>>(keys, x, wq, bq, bn_gamma, bn_beta,
                                              bn_mean, bn_var);
    // launch 2
    qproj_mma_kernel<<<dim3(T_TOK / 128, QDIM / 64), 256, DO_TOTAL>>>();
    // launch 3 (independent filler so scores lands at launch 4 for ncu)
    split_kernel<<<(HID_S * D_DIM / 4 + 255) / 256, 256>>>(s_w1, w1hi, w1lo, HID_S * D_DIM / 4);
    // launch 4: the kernel we need profiled
    scores_mma_kernel<<<dim3(T_TOK / TOK_TILE, H_HEADS, KEY_SPLITS), 256, SMS_TOTAL>>>();
    // remaining
    split_kernel<<<(HID_S * D_DIM / 4 + 255) / 256, 256>>>(s_w3, w3hi, w3lo, HID_S * D_DIM / 4);
    split_kernel<<<(D_DIM * HID_S / 4 + 255) / 256, 256>>>(s_w2, w2hi, w2lo, D_DIM * HID_S / 4);
    rescore_kernel<<<T_TOK, 128>>>(keys);
    moe_small_kernel<<<T_TOK, 128>>>(x, w_down, w_up, a_w1, a_w2, a_w3);
    swiglu_mma_kernel<<<dim3(T_TOK / 128, HID_S / 64), 256, DW_TOTAL>>>();
    out_mma_kernel<<<dim3(T_TOK / 128, D_DIM / 64), 256, DO_TOTAL>>>(out);
}

// round 15
// speedup vs baseline: 1.4131x; 1.0939x over previous
#include <cuda_runtime.h>
#include <cuda_bf16.h>
#include <cfloat>
#include <math.h>
#include <cstdint>

#define T_TOK   2048
#define D_DIM   768
#define H_HEADS 4
#define N_KEYS  25600
#define KD      128
#define KNN     16
#define HID_A   44
#define HID_S   1024
#define QDIM    (H_HEADS*KD)   // 512
#define BN_EPS  1e-5f

#define KEY_SPLITS 4
#define KEYS_PER_SPLIT (N_KEYS / KEY_SPLITS)   // 6400
#define CHUNK_N 64
#define NCHUNK (KEYS_PER_SPLIT / CHUNK_N)      // 100
#define TOK_TILE 128
#define NCAND  (KEY_SPLITS * KNN)              // 64 candidates per (token, head)

// ---------------- scratch (device globals; no allocations allowed) ----------
__device__ __nv_bfloat16 g_qhi[T_TOK * QDIM];
__device__ float g_qf[T_TOK * QDIM];
__device__ __nv_bfloat16 g_khi[H_HEADS * N_KEYS * KD];
__device__ int   g_ptopi[T_TOK * H_HEADS * NCAND];
__device__ int   g_topidx[T_TOK * H_HEADS * KNN];
__device__ float g_gates[T_TOK * H_HEADS * KNN];
__device__ float g_comb[T_TOK];
__device__ float g_bnA[QDIM];
__device__ float g_bnB[QDIM];
// bf16 hi/lo operand splits
__device__ __nv_bfloat16 g_xhi[T_TOK * D_DIM];
__device__ __nv_bfloat16 g_xlo[T_TOK * D_DIM];
__device__ __nv_bfloat16 g_wqhi[QDIM * D_DIM];
__device__ __nv_bfloat16 g_wqlo[QDIM * D_DIM];
__device__ __nv_bfloat16 g_w1hi[HID_S * D_DIM];
__device__ __nv_bfloat16 g_w1lo[HID_S * D_DIM];
__device__ __nv_bfloat16 g_w3hi[HID_S * D_DIM];
__device__ __nv_bfloat16 g_w3lo[HID_S * D_DIM];
__device__ __nv_bfloat16 g_w2hi[D_DIM * HID_S];
__device__ __nv_bfloat16 g_w2lo[D_DIM * HID_S];
__device__ __nv_bfloat16 g_hidhi[T_TOK * HID_S];
__device__ __nv_bfloat16 g_hidlo[T_TOK * HID_S];

// ============================================================================
// helpers
// ============================================================================
__device__ __forceinline__ uint32_t smem_u32(const void* p) {
    uint32_t a;
    asm("{ .reg .u64 t; cvta.to.shared.u64 t, %1; cvt.u32.u64 %0, t; }" : "=r"(a) : "l"(p));
    return a;
}
#define CP_ASYNC16(dst, src) \
    asm volatile("cp.async.cg.shared.global [%0], [%1], 16;" :: "r"((uint32_t)(dst)), "l"(src))
#define CP_COMMIT() asm volatile("cp.async.commit_group;" ::: "memory")
#define CP_WAIT0()  asm volatile("cp.async.wait_group 0;" ::: "memory")

__device__ __forceinline__ void ldmx4(uint32_t& r0, uint32_t& r1, uint32_t& r2, uint32_t& r3,
                                      uint32_t addr) {
    asm volatile("ldmatrix.sync.aligned.m8n8.x4.shared.b16 {%0,%1,%2,%3}, [%4];"
                 : "=r"(r0), "=r"(r1), "=r"(r2), "=r"(r3) : "r"(addr));
}
__device__ __forceinline__ void mma_bf16(float* c, const uint32_t* a, const uint32_t* b) {
    asm volatile(
        "mma.sync.aligned.m16n8k16.row.col.f32.bf16.bf16.f32 "
        "{%0,%1,%2,%3}, {%4,%5,%6,%7}, {%8,%9}, {%0,%1,%2,%3};"
        : "+f"(c[0]), "+f"(c[1]), "+f"(c[2]), "+f"(c[3])
        : "r"(a[0]), "r"(a[1]), "r"(a[2]), "r"(a[3]), "r"(b[0]), "r"(b[1]));
}

// fully unrolled register insertion into sorted-desc list of 16 floats+ints
__device__ __forceinline__ void reg_insert16(float* tv, int* ti, float vv, int idx) {
#pragma unroll
    for (int p = KNN - 1; p > 0; --p) {
        bool shift = tv[p - 1] < vv;
        bool here  = !shift && (tv[p] < vv);
        float ntv = shift ? tv[p - 1] : (here ? vv : tv[p]);
        int   nti = shift ? ti[p - 1] : (here ? idx : ti[p]);
        tv[p] = ntv; ti[p] = nti;
    }
    if (tv[0] < vv) { tv[0] = vv; ti[0] = idx; }
}

// ---- packed-key top-16 machinery (scores kernel) ----
// key = (sortable_bf16(v) << 16) | key_index   (idx < 65536)
#define INIT_KEY 0x007F0000u   // packed -inf

__device__ __forceinline__ uint32_t pack_key(float v, int idx) {
    uint32_t b = (uint32_t)__bfloat16_as_ushort(__float2bfloat16(v));
    uint32_t m = (b & 0x8000u) ? 0xFFFFu : 0x8000u;
    return ((b ^ m) << 16) | (uint32_t)idx;
}
__device__ __forceinline__ float unpack_min(uint32_t key15) {
    uint32_t s = key15 >> 16;
    uint32_t m = (s & 0x8000u) ? 0x8000u : 0xFFFFu;
    return __uint_as_float((s ^ m) << 16);
}
// sorted-desc insert on packed keys: 2 setp + 2 sel per slot
__device__ __forceinline__ void ins16u(uint32_t* L, uint32_t key) {
#pragma unroll
    for (int p = KNN - 1; p > 0; --p) {
        uint32_t up = L[p - 1];
        L[p] = (up < key) ? up : ((L[p] < key) ? key : L[p]);
    }
    if (L[0] < key) L[0] = key;
}

// ============================================================================
// prep_all: keysprep + split(x) + split(wq) + bnprep in one launch
// ============================================================================
#define PREP_KEY_BLKS ((H_HEADS * N_KEYS * KD) / (256 * 4))
#define PREP_X_BLKS   ((T_TOK * D_DIM) / (256 * 4))
#define PREP_WQ_BLKS  ((QDIM * D_DIM) / (256 * 4))
#define PREP_BN_BLKS  ((QDIM + 255) / 256)
#define PREP_TOTAL_BLKS (PREP_KEY_BLKS + PREP_X_BLKS + PREP_WQ_BLKS + PREP_BN_BLKS)

__global__ void prep_all_kernel(const float* __restrict__ keys,
                                const float* __restrict__ x,
                                const float* __restrict__ wq,
                                const float* __restrict__ bq,
                                const float* __restrict__ gamma,
                                const float* __restrict__ beta,
                                const float* __restrict__ mean,
                                const float* __restrict__ var)
{
    int b = blockIdx.x;
    if (b < PREP_KEY_BLKS) {
        size_t i = (size_t)b * 256 + threadIdx.x;
        const float4 v = ((const float4*)keys)[i];
        ((__nv_bfloat162*)g_khi)[2 * i] =
            __nv_bfloat162(__float2bfloat16(v.x), __float2bfloat16(v.y));
        ((__nv_bfloat162*)g_khi)[2 * i + 1] =
            __nv_bfloat162(__float2bfloat16(v.z), __float2bfloat16(v.w));
        return;
    }
    b -= PREP_KEY_BLKS;
    if (b < PREP_X_BLKS + PREP_WQ_BLKS) {
        const float* src;
        __nv_bfloat16 *hi, *lo;
        size_t i;
        if (b < PREP_X_BLKS) {
            src = x; hi = g_xhi; lo = g_xlo;
            i = (size_t)b * 256 + threadIdx.x;
        } else {
            src = wq; hi = g_wqhi; lo = g_wqlo;
            i = (size_t)(b - PREP_X_BLKS) * 256 + threadIdx.x;
        }
        float4 v = ((const float4*)src)[i];
        float f[4] = {v.x, v.y, v.z, v.w};
        __nv_bfloat16 h[4], l[4];
#pragma unroll
        for (int k = 0; k < 4; ++k) {
            h[k] = __float2bfloat16(f[k]);
            l[k] = __float2bfloat16(f[k] - __bfloat162float(h[k]));
        }
        ((__nv_bfloat162*)hi)[2 * i]     = __nv_bfloat162(h[0], h[1]);
        ((__nv_bfloat162*)hi)[2 * i + 1] = __nv_bfloat162(h[2], h[3]);
        ((__nv_bfloat162*)lo)[2 * i]     = __nv_bfloat162(l[0], l[1]);
        ((__nv_bfloat162*)lo)[2 * i + 1] = __nv_bfloat162(l[2], l[3]);
        return;
    }
    b -= PREP_X_BLKS + PREP_WQ_BLKS;
    {
        int n = b * 256 + threadIdx.x;
        if (n < QDIM) {
            float sc = gamma[n] * rsqrtf(var[n] + BN_EPS);
            g_bnA[n] = sc;
            g_bnB[n] = (bq[n] - mean[n]) * sc + beta[n];
        }
    }
}

// ============================================================================
// split: fp32 -> bf16 hi + lo residual
// ============================================================================
__global__ void split_kernel(const float* __restrict__ src,
                             __nv_bfloat16* __restrict__ hi,
                             __nv_bfloat16* __restrict__ lo, int n4)
{
    int i = blockIdx.x * 256 + threadIdx.x;
    if (i >= n4) return;
    float4 v = ((const float4*)src)[i];
    float f[4] = {v.x, v.y, v.z, v.w};
    __nv_bfloat16 h[4], l[4];
#pragma unroll
    for (int k = 0; k < 4; ++k) {
        h[k] = __float2bfloat16(f[k]);
        l[k] = __float2bfloat16(f[k] - __bfloat162float(h[k]));
    }
    ((__nv_bfloat162*)hi)[2 * i]     = __nv_bfloat162(h[0], h[1]);
    ((__nv_bfloat162*)hi)[2 * i + 1] = __nv_bfloat162(h[2], h[3]);
    ((__nv_bfloat162*)lo)[2 * i]     = __nv_bfloat162(l[0], l[1]);
    ((__nv_bfloat162*)lo)[2 * i + 1] = __nv_bfloat162(l[2], l[3]);
}

// ============================================================================
#define AB_STRIDE 272

// ============================================================================
// Kernel 1: qproj via HMMA 4-term split (unchanged)
// ============================================================================
#define DO_AH 0
#define DO_AL 34816
#define DO_BH 69632
#define DO_BL (69632 + 17408)
#define DO_TOTAL (69632 + 2*17408)   // 104448

__global__ void __launch_bounds__(256, 2) qproj_mma_kernel()
{
    extern __shared__ char smem[];
    const uint32_t smb = smem_u32(smem);
    const int tid  = threadIdx.x;
    const int wid  = tid >> 5;
    const int lane = tid & 31;
    const int m0 = blockIdx.x * 128;
    const int n0 = blockIdx.y * 64;

    const int warp_m = wid >> 1;
    const int warp_n = wid & 1;

    const uint32_t a_row_off = (uint32_t)((warp_m * 32 + (lane & 15)) * AB_STRIDE + (lane >> 4) * 16);
    const uint32_t b_row_off = (uint32_t)((warp_n * 32 + (lane & 7) + ((lane >> 4) << 3)) * AB_STRIDE
                                          + ((lane >> 3) & 1) * 16);

    float C[2][4][4] = {};

    const char* axh = (const char*)(g_xhi + (size_t)m0 * D_DIM);
    const char* axl = (const char*)(g_xlo + (size_t)m0 * D_DIM);
    const char* bh_ = (const char*)(g_wqhi + (size_t)n0 * D_DIM);
    const char* bl_ = (const char*)(g_wqlo + (size_t)n0 * D_DIM);

    for (int kc = 0; kc < D_DIM / 128; ++kc) {
        if (kc) __syncthreads();
        const uint32_t ko = (uint32_t)(kc * 256);
#pragma unroll
        for (int it = 0; it < 8; ++it) {
            int idx = tid + it * 256;
            int r = idx >> 4, seg = idx & 15;
            uint32_t d = (uint32_t)(r * AB_STRIDE + seg * 16);
            uint32_t s = (uint32_t)(r * (D_DIM * 2)) + ko + seg * 16;
            CP_ASYNC16(smb + DO_AH + d, axh + s);
            CP_ASYNC16(smb + DO_AL + d, axl + s);
        }
#pragma unroll
        for (int it = 0; it < 4; ++it) {
            int idx = tid + it * 256;
            int r = idx >> 4, seg = idx & 15;
            uint32_t d = (uint32_t)(r * AB_STRIDE + seg * 16);
            uint32_t s = (uint32_t)(r * (D_DIM * 2)) + ko + seg * 16;
            CP_ASYNC16(smb + DO_BH + d, bh_ + s);
            CP_ASYNC16(smb + DO_BL + d, bl_ + s);
        }
        CP_COMMIT(); CP_WAIT0();
        __syncthreads();

#pragma unroll
        for (int ks = 0; ks < 8; ++ks) {
            const uint32_t koff = (uint32_t)(ks * 32);
            uint32_t bH[8], bL[8];
            ldmx4(bH[0], bH[1], bH[2], bH[3], smb + DO_BH + b_row_off + koff);
            ldmx4(bH[4], bH[5], bH[6], bH[7], smb + DO_BH + b_row_off + koff + 16 * AB_STRIDE);
            ldmx4(bL[0], bL[1], bL[2], bL[3], smb + DO_BL + b_row_off + koff);
            ldmx4(bL[4], bL[5], bL[6], bL[7], smb + DO_BL + b_row_off + koff + 16 * AB_STRIDE);
#pragma unroll
            for (int i = 0; i < 2; ++i) {
                uint32_t ah[4], al[4];
                ldmx4(ah[0], ah[1], ah[2], ah[3],
                      smb + DO_AH + a_row_off + koff + (uint32_t)(i * 16 * AB_STRIDE));
                ldmx4(al[0], al[1], al[2], al[3],
                      smb + DO_AL + a_row_off + koff + (uint32_t)(i * 16 * AB_STRIDE));
#pragma unroll
                for (int j = 0; j < 4; ++j) {
                    mma_bf16(C[i][j], ah, bH + 2 * j);
                    mma_bf16(C[i][j], ah, bL + 2 * j);
                    mma_bf16(C[i][j], al, bH + 2 * j);
                    mma_bf16(C[i][j], al, bL + 2 * j);
                }
            }
        }
    }

    const int trow = lane >> 2;
    const int tcol = (lane & 3) * 2;
#pragma unroll
    for (int i = 0; i < 2; ++i) {
#pragma unroll
        for (int half = 0; half < 2; ++half) {
            int m = m0 + warp_m * 32 + i * 16 + trow + half * 8;
#pragma unroll
            for (int j = 0; j < 4; ++j) {
                int n = n0 + warp_n * 32 + j * 8 + tcol;
                float va = C[i][j][2 * half]     * g_bnA[n]     + g_bnB[n];
                float vb = C[i][j][2 * half + 1] * g_bnA[n + 1] + g_bnB[n + 1];
                *(float2*)(g_qf + (size_t)m * QDIM + n) = make_float2(va, vb);
                *(__nv_bfloat162*)(g_qhi + (size_t)m * QDIM + n) =
                    __nv_bfloat162(__float2bfloat16(va), __float2bfloat16(vb));
            }
        }
    }
}

// ============================================================================
// Kernel 2: pass-1 scores — register scan, packed-key lists, SHARED
// token-level thresholds (max of lane minima over each 4-lane token group,
// refreshed once per chunk). 256 threads, 8 warps x (16 tok x 64 keys).
// ============================================================================
#define SMS_A     0            // 128*272 = 34816
#define SMS_B0    34816        // 64*272 = 17408
#define SMS_B1    52224
#define SMS_TOTAL 69632

__global__ void __launch_bounds__(256, 2) scores_mma_kernel()
{
    extern __shared__ char smem[];
    const uint32_t smb = smem_u32(smem);
    const int tid  = threadIdx.x;
    const int wid  = tid >> 5;       // 0..7 -> tokens 16*wid
    const int lane = tid & 31;

    const int t0 = blockIdx.x * TOK_TILE;
    const int h  = blockIdx.y;
    const int z  = blockIdx.z;
    const int keybase = z * KEYS_PER_SPLIT;

    uint32_t bdst[4], bsrc[4];
#pragma unroll
    for (int i = 0; i < 4; ++i) {
        int idx = tid + i * 256;
        int r = idx >> 4, seg = idx & 15;
        bdst[i] = (uint32_t)(r * AB_STRIDE + seg * 16);
        bsrc[i] = (uint32_t)(r * 256 + seg * 16);
    }

    {
        const char* qh = (const char*)(g_qhi + (size_t)t0 * QDIM + h * KD);
#pragma unroll
        for (int i = 0; i < 8; ++i) {
            int idx = tid + i * 256;
            int r = idx >> 4, seg = idx & 15;
            CP_ASYNC16(smb + SMS_A + (uint32_t)(r * AB_STRIDE + seg * 16),
                       qh + (size_t)r * (QDIM * 2) + seg * 16);
        }
    }
    const char* khbase = (const char*)(g_khi + ((size_t)h * N_KEYS + keybase) * KD);
    {
#pragma unroll
        for (int i = 0; i < 4; ++i) CP_ASYNC16(smb + SMS_B0 + bdst[i], khbase + bsrc[i]);
        CP_COMMIT();
    }

    // packed top-16 lists: streams A (row trow) and B (row trow+8)
    uint32_t LA[KNN], LB[KNN];
#pragma unroll
    for (int k = 0; k < KNN; ++k) { LA[k] = INIT_KEY; LB[k] = INIT_KEY; }
    float minvA = -FLT_MAX, minvB = -FLT_MAX;   // shared token thresholds

    const uint32_t a_row_off = (uint32_t)((wid * 16 + (lane & 15)) * AB_STRIDE + (lane >> 4) * 16);
    const uint32_t b_row_off = (uint32_t)(((lane & 7) + ((lane >> 4) << 3)) * AB_STRIDE
                                          + ((lane >> 3) & 1) * 16);

    const int tcol = (lane & 3) * 2;

    for (int c = 0; c < NCHUNK; ++c) {
        const uint32_t bbase = (c & 1) ? (smb + SMS_B1) : (smb + SMS_B0);
        CP_WAIT0();
        __syncthreads();

        if (c + 1 < NCHUNK) {
            const uint32_t obase = (c & 1) ? (smb + SMS_B0) : (smb + SMS_B1);
            const uint32_t cb = (uint32_t)((c + 1) * CHUNK_N * KD * 2);
#pragma unroll
            for (int i = 0; i < 4; ++i) CP_ASYNC16(obase + bdst[i], khbase + cb + bsrc[i]);
            CP_COMMIT();
        }

        float C[8][4];
#pragma unroll
        for (int j = 0; j < 8; ++j)
#pragma unroll
            for (int e = 0; e < 4; ++e) C[j][e] = 0.f;

#pragma unroll
        for (int ks = 0; ks < 8; ++ks) {
            const uint32_t koff = (uint32_t)(ks * 32);
            uint32_t bh[16], ah[4];
            ldmx4(bh[0],  bh[1],  bh[2],  bh[3],  bbase + b_row_off + koff);
            ldmx4(bh[4],  bh[5],  bh[6],  bh[7],  bbase + b_row_off + koff + 16 * AB_STRIDE);
            ldmx4(bh[8],  bh[9],  bh[10], bh[11], bbase + b_row_off + koff + 32 * AB_STRIDE);
            ldmx4(bh[12], bh[13], bh[14], bh[15], bbase + b_row_off + koff + 48 * AB_STRIDE);
            ldmx4(ah[0], ah[1], ah[2], ah[3], smb + SMS_A + a_row_off + koff);
#pragma unroll
            for (int j = 0; j < 8; ++j) mma_bf16(C[j], ah, bh + 2 * j);
        }

        // scan with SHARED thresholds: insert iff v >= T (conservative, exact)
        const int kb = keybase + c * CHUNK_N + tcol;
#pragma unroll
        for (int j = 0; j < 8; ++j) {
            const int i0 = kb + j * 8, i1 = i0 + 1;
            float v0 = C[j][0], v1 = C[j][1];
            if (fmaxf(v0, v1) >= minvA) {
                if (v0 >= minvA) ins16u(LA, pack_key(v0, i0));
                if (v1 >= minvA) ins16u(LA, pack_key(v1, i1));
            }
            float v2 = C[j][2], v3 = C[j][3];
            if (fmaxf(v2, v3) >= minvB) {
                if (v2 >= minvB) ins16u(LB, pack_key(v2, i0));
                if (v3 >= minvB) ins16u(LB, pack_key(v3, i1));
            }
        }

        // refresh shared thresholds: max of lane minima over 4-lane token group
        {
            float mA = unpack_min(LA[KNN - 1]);
            mA = fmaxf(mA, __shfl_xor_sync(0xffffffffu, mA, 1));
            mA = fmaxf(mA, __shfl_xor_sync(0xffffffffu, mA, 2));
            minvA = mA;
            float mB = unpack_min(LB[KNN - 1]);
            mB = fmaxf(mB, __shfl_xor_sync(0xffffffffu, mB, 1));
            mB = fmaxf(mB, __shfl_xor_sync(0xffffffffu, mB, 2));
            minvB = mB;
        }
    }

    // merge the 4 lanes of each trow group (lanes 4t..4t+3) via shfl
    {
        uint32_t ov[KNN];
        // ---- list A ----
#pragma unroll
        for (int k = 0; k < KNN; ++k) ov[k] = __shfl_down_sync(0xffffffffu, LA[k], 1);
        if ((lane & 1) == 0) {
#pragma unroll
            for (int k = 0; k < KNN; ++k)
                if (ov[k] > LA[KNN - 1]) ins16u(LA, ov[k]);
        }
#pragma unroll
        for (int k = 0; k < KNN; ++k) ov[k] = __shfl_down_sync(0xffffffffu, LA[k], 2);
        if ((lane & 3) == 0) {
#pragma unroll
            for (int k = 0; k < KNN; ++k)
                if (ov[k] > LA[KNN - 1]) ins16u(LA, ov[k]);
        }
        // ---- list B ----
#pragma unroll
        for (int k = 0; k < KNN; ++k) ov[k] = __shfl_down_sync(0xffffffffu, LB[k], 1);
        if ((lane & 1) == 0) {
#pragma unroll
            for (int k = 0; k < KNN; ++k)
                if (ov[k] > LB[KNN - 1]) ins16u(LB, ov[k]);
        }
#pragma unroll
        for (int k = 0; k < KNN; ++k) ov[k] = __shfl_down_sync(0xffffffffu, LB[k], 2);
        if ((lane & 3) == 0) {
#pragma unroll
            for (int k = 0; k < KNN; ++k)
                if (ov[k] > LB[KNN - 1]) ins16u(LB, ov[k]);
            int tA = t0 + wid * 16 + (lane >> 2);
            int tB = tA + 8;
            size_t pbA = (((size_t)tA * H_HEADS + h) * KEY_SPLITS + z) * KNN;
            size_t pbB = (((size_t)tB * H_HEADS + h) * KEY_SPLITS + z) * KNN;
#pragma unroll
            for (int k = 0; k < KNN; ++k) {
                g_ptopi[pbA + k] = (int)(LA[k] & 0xFFFFu);
                g_ptopi[pbB + k] = (int)(LB[k] & 0xFFFFu);
            }
        }
    }
}

// ============================================================================
// Kernel 2b: exact fp32 rescore of 64 candidates (unchanged)
// ============================================================================
__global__ void __launch_bounds__(128) rescore_kernel(const float* __restrict__ keys)
{
    const int t = blockIdx.x;
    const int h = threadIdx.x >> 5;
    const int lane = threadIdx.x & 31;
    const int bh = t * H_HEADS + h;

    __shared__ float sq[H_HEADS][KD];
    *(float4*)(&sq[h][lane * 4]) = *(const float4*)(g_qf + (size_t)t * QDIM + h * KD + lane * 4);
    __syncwarp();

    const int idx0 = g_ptopi[(size_t)bh * NCAND + lane];
    const int idx1 = g_ptopi[(size_t)bh * NCAND + 32 + lane];
    const float4* kr0 = (const float4*)(keys + ((size_t)h * N_KEYS + idx0) * KD);
    const float4* kr1 = (const float4*)(keys + ((size_t)h * N_KEYS + idx1) * KD);
    float acc0 = 0.f, acc1 = 0.f;
#pragma unroll
    for (int d4 = 0; d4 < KD / 4; ++d4) {
        float4 k0 = kr0[d4], k1 = kr1[d4];
        float q0 = sq[h][4 * d4 + 0], q1 = sq[h][4 * d4 + 1];
        float q2 = sq[h][4 * d4 + 2], q3 = sq[h][4 * d4 + 3];
        acc0 = fmaf(k0.x, q0, acc0); acc0 = fmaf(k0.y, q1, acc0);
        acc0 = fmaf(k0.z, q2, acc0); acc0 = fmaf(k0.w, q3, acc0);
        acc1 = fmaf(k1.x, q0, acc1); acc1 = fmaf(k1.y, q1, acc1);
        acc1 = fmaf(k1.z, q2, acc1); acc1 = fmaf(k1.w, q3, acc1);
    }

    int rank0 = 0, rank1 = 0;
#pragma unroll
    for (int j = 0; j < 32; ++j) {
        float v0 = __shfl_sync(0xffffffffu, acc0, j);
        float v1 = __shfl_sync(0xffffffffu, acc1, j);
        rank0 += (v0 > acc0) || (v0 == acc0 && j < lane);
        rank0 += (v1 > acc0);
        rank1 += (v0 > acc1) || (v0 == acc1);
        rank1 += (v1 > acc1) || (v1 == acc1 && j < lane);
    }

    float vmax = fmaxf(acc0, acc1);
#pragma unroll
    for (int off = 16; off > 0; off >>= 1)
        vmax = fmaxf(vmax, __shfl_xor_sync(0xffffffffu, vmax, off));
    float e0 = (rank0 < KNN) ? __expf(acc0 - vmax) : 0.f;
    float e1 = (rank1 < KNN) ? __expf(acc1 - vmax) : 0.f;
    float sum = e0 + e1;
#pragma unroll
    for (int off = 16; off > 0; off >>= 1)
        sum += __shfl_xor_sync(0xffffffffu, sum, off);
    float inv = 1.f / sum;
    if (rank0 < KNN) {
        g_gates[(size_t)bh * KNN + rank0]  = e0 * inv;
        g_topidx[(size_t)bh * KNN + rank0] = idx0;
    }
    if (rank1 < KNN) {
        g_gates[(size_t)bh * KNN + rank1]  = e1 * inv;
        g_topidx[(size_t)bh * KNN + rank1] = idx1;
    }
}

// ============================================================================
// Kernel 3: tiny PEER expert network per token (unchanged)
// ============================================================================
__global__ void moe_small_kernel(const float* __restrict__ x,
                                 const float* __restrict__ wdown,
                                 const float* __restrict__ wup,
                                 const float* __restrict__ aw1,
                                 const float* __restrict__ aw2,
                                 const float* __restrict__ aw3)
{
    __shared__ float s_aw1[HID_A * KNN];
    __shared__ float s_aw3[HID_A * KNN];
    __shared__ float s_aw2[KNN * HID_A];
    __shared__ float s_z[H_HEADS][KNN];
    __shared__ float s_hid[H_HEADS][HID_A];
    __shared__ float s_red[H_HEADS];
    __shared__ float s_wred[4];
    __shared__ float s_xsum;

    const int t = blockIdx.x;
    const int tid = threadIdx.x;
    const int w = tid >> 5;
    const int lane = tid & 31;

    for (int i = tid; i < HID_A * KNN; i += 128) { s_aw1[i] = aw1[i]; s_aw3[i] = aw3[i]; s_aw2[i] = aw2[i]; }

    float ps = 0.f;
    for (int i = tid; i < D_DIM; i += 128) ps += x[(size_t)t * D_DIM + i];
#pragma unroll
    for (int off = 16; off > 0; off >>= 1) ps += __shfl_down_sync(0xffffffffu, ps, off);
    if (lane == 0) s_wred[w] = ps;
    __syncthreads();
    if (tid == 0) s_xsum = s_wred[0] + s_wred[1] + s_wred[2] + s_wred[3];
    __syncthreads();
    const float xsum = s_xsum;

    const size_t gbase = ((size_t)t * H_HEADS + w) * KNN;
    if (lane < KNN)
        s_z[w][lane] = xsum * wdown[g_topidx[gbase + lane]];
    __syncwarp();

    for (int a = lane; a < HID_A; a += 32) {
        float d1 = 0.f, d3 = 0.f;
#pragma unroll
        for (int k = 0; k < KNN; ++k) {
            float zz = s_z[w][k];
            d1 = fmaf(zz, s_aw1[a * KNN + k], d1);
            d3 = fmaf(zz, s_aw3[a * KNN + k], d3);
        }
        float sl = d1 / (1.f + __expf(-d1));
        s_hid[w][a] = sl * d3;
    }
    __syncwarp();

    float part = 0.f;
    if (lane < KNN) {
        float o = 0.f;
#pragma unroll
        for (int a = 0; a < HID_A; ++a) o = fmaf(s_hid[w][a], s_aw2[lane * HID_A + a], o);
        int id = g_topidx[gbase + lane];
        part = o * g_gates[gbase + lane] * wup[id];
    }
#pragma unroll
    for (int off = 16; off > 0; off >>= 1) part += __shfl_down_sync(0xffffffffu, part, off);
    if (lane == 0) s_red[w] = part;
    __syncthreads();
    if (tid == 0) g_comb[t] = s_red[0] + s_red[1] + s_red[2] + s_red[3];
}

// ============================================================================
// Kernel 4: swiglu via HMMA 3-term split (unchanged)
// ============================================================================
#define DW_AH 0
#define DW_AL 34816
#define DW_B  69632
#define DW_BSZ 17408
#define DW_TOTAL (DW_B + 4*DW_BSZ)

__global__ void __launch_bounds__(256, 1) swiglu_mma_kernel()
{
    extern __shared__ char smem[];
    const uint32_t smb = smem_u32(smem);
    const int tid  = threadIdx.x;
    const int wid  = tid >> 5;
    const int lane = tid & 31;
    const int m0 = blockIdx.x * 128;
    const int n0 = blockIdx.y * 64;

    const int warp_m = wid >> 1;
    const int warp_n = wid & 1;

    const uint32_t a_row_off = (uint32_t)((warp_m * 32 + (lane & 15)) * AB_STRIDE + (lane >> 4) * 16);
    const uint32_t b_row_off = (uint32_t)((warp_n * 32 + (lane & 7) + ((lane >> 4) << 3)) * AB_STRIDE
                                          + ((lane >> 3) & 1) * 16);

    float C1[2][4][4] = {};
    float C3[2][4][4] = {};

    const char* axh = (const char*)(g_xhi + (size_t)m0 * D_DIM);
    const char* axl = (const char*)(g_xlo + (size_t)m0 * D_DIM);
    const char* b1h = (const char*)(g_w1hi + (size_t)n0 * D_DIM);
    const char* b1l = (const char*)(g_w1lo + (size_t)n0 * D_DIM);
    const char* b3h = (const char*)(g_w3hi + (size_t)n0 * D_DIM);
    const char* b3l = (const char*)(g_w3lo + (size_t)n0 * D_DIM);

    for (int kc = 0; kc < D_DIM / 128; ++kc) {
        if (kc) __syncthreads();
        const uint32_t ko = (uint32_t)(kc * 256);
#pragma unroll
        for (int it = 0; it < 8; ++it) {
            int idx = tid + it * 256;
            int r = idx >> 4, seg = idx & 15;
            uint32_t d = (uint32_t)(r * AB_STRIDE + seg * 16);
            uint32_t s = (uint32_t)(r * (D_DIM * 2)) + ko + seg * 16;
            CP_ASYNC16(smb + DW_AH + d, axh + s);
            CP_ASYNC16(smb + DW_AL + d, axl + s);
        }
#pragma unroll
        for (int it = 0; it < 4; ++it) {
            int idx = tid + it * 256;
            int r = idx >> 4, seg = idx & 15;
            uint32_t d = (uint32_t)(r * AB_STRIDE + seg * 16);
            uint32_t s = (uint32_t)(r * (D_DIM * 2)) + ko + seg * 16;
            CP_ASYNC16(smb + DW_B + 0 * DW_BSZ + d, b1h + s);
            CP_ASYNC16(smb + DW_B + 1 * DW_BSZ + d, b1l + s);
            CP_ASYNC16(smb + DW_B + 2 * DW_BSZ + d, b3h + s);
            CP_ASYNC16(smb + DW_B + 3 * DW_BSZ + d, b3l + s);
        }
        CP_COMMIT(); CP_WAIT0();
        __syncthreads();

#pragma unroll
        for (int ks = 0; ks < 8; ++ks) {
            const uint32_t koff = (uint32_t)(ks * 32);
            uint32_t b1H[8], b1L[8], b3H[8], b3L[8];
            ldmx4(b1H[0], b1H[1], b1H[2], b1H[3], smb + DW_B + 0 * DW_BSZ + b_row_off + koff);
            ldmx4(b1H[4], b1H[5], b1H[6], b1H[7], smb + DW_B + 0 * DW_BSZ + b_row_off + koff + 16 * AB_STRIDE);
            ldmx4(b1L[0], b1L[1], b1L[2], b1L[3], smb + DW_B + 1 * DW_BSZ + b_row_off + koff);
            ldmx4(b1L[4], b1L[5], b1L[6], b1L[7], smb + DW_B + 1 * DW_BSZ + b_row_off + koff + 16 * AB_STRIDE);
            ldmx4(b3H[0], b3H[1], b3H[2], b3H[3], smb + DW_B + 2 * DW_BSZ + b_row_off + koff);
            ldmx4(b3H[4], b3H[5], b3H[6], b3H[7], smb + DW_B + 2 * DW_BSZ + b_row_off + koff + 16 * AB_STRIDE);
            ldmx4(b3L[0], b3L[1], b3L[2], b3L[3], smb + DW_B + 3 * DW_BSZ + b_row_off + koff);
            ldmx4(b3L[4], b3L[5], b3L[6], b3L[7], smb + DW_B + 3 * DW_BSZ + b_row_off + koff + 16 * AB_STRIDE);
#pragma unroll
            for (int i = 0; i < 2; ++i) {
                uint32_t ah[4], al[4];
                ldmx4(ah[0], ah[1], ah[2], ah[3],
                      smb + DW_AH + a_row_off + koff + (uint32_t)(i * 16 * AB_STRIDE));
                ldmx4(al[0], al[1], al[2], al[3],
                      smb + DW_AL + a_row_off + koff + (uint32_t)(i * 16 * AB_STRIDE));
#pragma unroll
                for (int j = 0; j < 4; ++j) {
                    mma_bf16(C1[i][j], ah, b1H + 2 * j);
                    mma_bf16(C1[i][j], ah, b1L + 2 * j);
                    mma_bf16(C1[i][j], al, b1H + 2 * j);
                    mma_bf16(C3[i][j], ah, b3H + 2 * j);
                    mma_bf16(C3[i][j], ah, b3L + 2 * j);
                    mma_bf16(C3[i][j], al, b3H + 2 * j);
                }
            }
        }
    }

    const int trow = lane >> 2;
    const int tcol = (lane & 3) * 2;
#pragma unroll
    for (int i = 0; i < 2; ++i) {
#pragma unroll
        for (int j = 0; j < 4; ++j) {
            int n = n0 + warp_n * 32 + j * 8 + tcol;
#pragma unroll
            for (int half = 0; half < 2; ++half) {
                int m = m0 + warp_m * 32 + i * 16 + trow + half * 8;
                float z1a = C1[i][j][2 * half], z1b = C1[i][j][2 * half + 1];
                float z3a = C3[i][j][2 * half], z3b = C3[i][j][2 * half + 1];
                float va = (z1a / (1.f + __expf(-z1a))) * z3a;
                float vb = (z1b / (1.f + __expf(-z1b))) * z3b;
                __nv_bfloat16 ha = __float2bfloat16(va);
                __nv_bfloat16 hb = __float2bfloat16(vb);
                __nv_bfloat16 la = __float2bfloat16(va - __bfloat162float(ha));
                __nv_bfloat16 lb = __float2bfloat16(vb - __bfloat162float(hb));
                *(__nv_bfloat162*)(g_hidhi + (size_t)m * HID_S + n) = __nv_bfloat162(ha, hb);
                *(__nv_bfloat162*)(g_hidlo + (size_t)m * HID_S + n) = __nv_bfloat162(la, lb);
            }
        }
    }
}

// ============================================================================
// Kernel 5: out = hid @ w2^T + comb (unchanged)
// ============================================================================
__global__ void __launch_bounds__(256, 1) out_mma_kernel(float* __restrict__ out)
{
    extern __shared__ char smem[];
    const uint32_t smb = smem_u32(smem);
    const int tid  = threadIdx.x;
    const int wid  = tid >> 5;
    const int lane = tid & 31;
    const int m0 = blockIdx.x * 128;
    const int n0 = blockIdx.y * 64;

    const int warp_m = wid >> 1;
    const int warp_n = wid & 1;

    const uint32_t a_row_off = (uint32_t)((warp_m * 32 + (lane & 15)) * AB_STRIDE + (lane >> 4) * 16);
    const uint32_t b_row_off = (uint32_t)((warp_n * 32 + (lane & 7) + ((lane >> 4) << 3)) * AB_STRIDE
                                          + ((lane >> 3) & 1) * 16);

    float C[2][4][4] = {};

    const char* axh = (const char*)(g_hidhi + (size_t)m0 * HID_S);
    const char* axl = (const char*)(g_hidlo + (size_t)m0 * HID_S);
    const char* bh_ = (const char*)(g_w2hi + (size_t)n0 * HID_S);
    const char* bl_ = (const char*)(g_w2lo + (size_t)n0 * HID_S);

    for (int kc = 0; kc < HID_S / 128; ++kc) {
        if (kc) __syncthreads();
        const uint32_t ko = (uint32_t)(kc * 256);
#pragma unroll
        for (int it = 0; it < 8; ++it) {
            int idx = tid + it * 256;
            int r = idx >> 4, seg = idx & 15;
            uint32_t d = (uint32_t)(r * AB_STRIDE + seg * 16);
            uint32_t s = (uint32_t)(r * (HID_S * 2)) + ko + seg * 16;
            CP_ASYNC16(smb + DO_AH + d, axh + s);
            CP_ASYNC16(smb + DO_AL + d, axl + s);
        }
#pragma unroll
        for (int it = 0; it < 4; ++it) {
            int idx = tid + it * 256;
            int r = idx >> 4, seg = idx & 15;
            uint32_t d = (uint32_t)(r * AB_STRIDE + seg * 16);
            uint32_t s = (uint32_t)(r * (HID_S * 2)) + ko + seg * 16;
            CP_ASYNC16(smb + DO_BH + d, bh_ + s);
            CP_ASYNC16(smb + DO_BL + d, bl_ + s);
        }
        CP_COMMIT(); CP_WAIT0();
        __syncthreads();

#pragma unroll
        for (int ks = 0; ks < 8; ++ks) {
            const uint32_t koff = (uint32_t)(ks * 32);
            uint32_t bH[8], bL[8];
            ldmx4(bH[0], bH[1], bH[2], bH[3], smb + DO_BH + b_row_off + koff);
            ldmx4(bH[4], bH[5], bH[6], bH[7], smb + DO_BH + b_row_off + koff + 16 * AB_STRIDE);
            ldmx4(bL[0], bL[1], bL[2], bL[3], smb + DO_BL + b_row_off + koff);
            ldmx4(bL[4], bL[5], bL[6], bL[7], smb + DO_BL + b_row_off + koff + 16 * AB_STRIDE);
#pragma unroll
            for (int i = 0; i < 2; ++i) {
                uint32_t ah[4], al[4];
                ldmx4(ah[0], ah[1], ah[2], ah[3],
                      smb + DO_AH + a_row_off + koff + (uint32_t)(i * 16 * AB_STRIDE));
                ldmx4(al[0], al[1], al[2], al[3],
                      smb + DO_AL + a_row_off + koff + (uint32_t)(i * 16 * AB_STRIDE));
#pragma unroll
                for (int j = 0; j < 4; ++j) {
                    mma_bf16(C[i][j], ah, bH + 2 * j);
                    mma_bf16(C[i][j], ah, bL + 2 * j);
                    mma_bf16(C[i][j], al, bH + 2 * j);
                }
            }
        }
    }

    const int trow = lane >> 2;
    const int tcol = (lane & 3) * 2;
#pragma unroll
    for (int i = 0; i < 2; ++i) {
#pragma unroll
        for (int half = 0; half < 2; ++half) {
            int m = m0 + warp_m * 32 + i * 16 + trow + half * 8;
            float cb = g_comb[m];
#pragma unroll
            for (int j = 0; j < 4; ++j) {
                int n = n0 + warp_n * 32 + j * 8 + tcol;
                *(float2*)(out + (size_t)m * D_DIM + n) =
                    make_float2(C[i][j][2 * half] + cb, C[i][j][2 * half + 1] + cb);
            }
        }
    }
}

// ============================================================================
extern "C" void kernel_launch(void* const* d_in, const int* in_sizes, int n_in,
                              void* d_out, int out_size)
{
    const float* x        = (const float*)d_in[0];
    const float* wq       = (const float*)d_in[1];
    const float* bq       = (const float*)d_in[2];
    const float* bn_gamma = (const float*)d_in[3];
    const float* bn_beta  = (const float*)d_in[4];
    const float* bn_mean  = (const float*)d_in[5];
    const float* bn_var   = (const float*)d_in[6];
    const float* keys     = (const float*)d_in[7];
    const float* w_down   = (const float*)d_in[8];
    const float* w_up     = (const float*)d_in[9];
    const float* a_w1     = (const float*)d_in[10];
    const float* a_w2     = (const float*)d_in[11];
    const float* a_w3     = (const float*)d_in[12];
    const float* s_w1     = (const float*)d_in[13];
    const float* s_w2     = (const float*)d_in[14];
    const float* s_w3     = (const float*)d_in[15];
    float* out            = (float*)d_out;

    __nv_bfloat16 *w1hi, *w1lo, *w3hi, *w3lo, *w2hi, *w2lo;
    cudaGetSymbolAddress((void**)&w1hi, g_w1hi); cudaGetSymbolAddress((void**)&w1lo, g_w1lo);
    cudaGetSymbolAddress((void**)&w3hi, g_w3hi); cudaGetSymbolAddress((void**)&w3lo, g_w3lo);
    cudaGetSymbolAddress((void**)&w2hi, g_w2hi); cudaGetSymbolAddress((void**)&w2lo, g_w2lo);

    cudaFuncSetAttribute(scores_mma_kernel,
                         cudaFuncAttributeMaxDynamicSharedMemorySize, SMS_TOTAL);
    cudaFuncSetAttribute(qproj_mma_kernel,
                         cudaFuncAttributeMaxDynamicSharedMemorySize, DO_TOTAL);
    cudaFuncSetAttribute(swiglu_mma_kernel,
                         cudaFuncAttributeMaxDynamicSharedMemorySize, DW_TOTAL);
    cudaFuncSetAttribute(out_mma_kernel,
                         cudaFuncAttributeMaxDynamicSharedMemorySize, DO_TOTAL);

    // launch 1: all pre-qproj prep fused
    prep_all_kernel<<<PREP_TOTAL_BLKS, 256>>>(keys, x, wq, bq, bn_gamma, bn_beta,
                                              bn_mean, bn_var);
    // launch 2
    qproj_mma_kernel<<<dim3(T_TOK / 128, QDIM / 64), 256, DO_TOTAL>>>();
    // launch 3 (independent filler so scores lands at launch 4 for ncu)
    split_kernel<<<(HID_S * D_DIM / 4 + 255) / 256, 256>>>(s_w1, w1hi, w1lo, HID_S * D_DIM / 4);
    // launch 4: the kernel we need profiled
    scores_mma_kernel<<<dim3(T_TOK / TOK_TILE, H_HEADS, KEY_SPLITS), 256, SMS_TOTAL>>>();
    // remaining
    split_kernel<<<(HID_S * D_DIM / 4 + 255) / 256, 256>>>(s_w3, w3hi, w3lo, HID_S * D_DIM / 4);
    split_kernel<<<(D_DIM * HID_S / 4 + 255) / 256, 256>>>(s_w2, w2hi, w2lo, D_DIM * HID_S / 4);
    rescore_kernel<<<T_TOK, 128>>>(keys);
    moe_small_kernel<<<T_TOK, 128>>>(x, w_down, w_up, a_w1, a_w2, a_w3);
    swiglu_mma_kernel<<<dim3(T_TOK / 128, HID_S / 64), 256, DW_TOTAL>>>();
    out_mma_kernel<<<dim3(T_TOK / 128, D_DIM / 64), 256, DO_TOTAL>>>(out);
}